// round 13
// baseline (speedup 1.0000x reference)
#include <cuda_runtime.h>
#include <cuda_bf16.h>
#include <cstdint>
#include <cstddef>

// ---------------- problem constants ----------------
#define B_   4
#define S_   1024
#define H_   12
#define DH_  64
#define E_   768
#define DM_  768
#define T_   (B_ * S_)            // 4096 tokens
#define KP   2304                 // triple-expanded K for the big GEMMs
#define KH   192                  // triple-expanded head dim (3*64)
#define SQK  0.125f               // 1/sqrt(64)
#define WOFF ((size_t)B_ * S_ * H_ * S_)   // start of y in d_out

// ---------------- scratch (device globals; no allocation) ----------------
__device__ float g_y [T_ * DM_];
__device__ float g_m [B_ * H_ * S_];
__device__ float g_l [B_ * H_ * S_];
__device__ float g_V [B_ * H_ * S_ * DH_];          // V fp32 [bh][s][64]
// triple-expanded bf16 operands
__device__ __nv_bfloat16 g_xi [T_ * KP];            // x tokens (A order)
__device__ __nv_bfloat16 g_ai [T_ * KP];            // ctx tokens (A order)
__device__ __nv_bfloat16 g_wb [3 * DM_ * KP];       // qkv weights (B order)
__device__ __nv_bfloat16 g_wdb[DM_ * KP];           // dense weights (B order)
// attention operands
__device__ __nv_bfloat16 g_Qi [B_ * H_ * S_ * KH];  // Q A-triples [bh][s][192]
__device__ __nv_bfloat16 g_Ki [B_ * H_ * S_ * KH];  // K B-triples [bh][s][192]
__device__ __nv_bfloat16 g_Vt [B_ * H_ * DH_ * 3 * S_]; // V B-triples [bh][d][3s]

// ---------------- mma.sync / ldmatrix / cp.async helpers ----------------
typedef unsigned long long ull;

__device__ __forceinline__ uint32_t smem_u32(const void* p) {
    uint32_t a;
    asm("{ .reg .u64 t; cvta.to.shared.u64 t, %1; cvt.u32.u64 %0, t; }"
        : "=r"(a) : "l"(p));
    return a;
}
__device__ __forceinline__ void ldsm4(uint32_t r[4], uint32_t addr) {
    asm volatile("ldmatrix.sync.aligned.m8n8.x4.shared.b16 {%0,%1,%2,%3}, [%4];"
                 : "=r"(r[0]), "=r"(r[1]), "=r"(r[2]), "=r"(r[3]) : "r"(addr));
}
__device__ __forceinline__ void mma_bf16(float d[4], const uint32_t a[4],
                                         uint32_t b0, uint32_t b1) {
    asm volatile(
        "mma.sync.aligned.m16n8k16.row.col.f32.bf16.bf16.f32 "
        "{%0,%1,%2,%3}, {%4,%5,%6,%7}, {%8,%9}, {%0,%1,%2,%3};"
        : "+f"(d[0]), "+f"(d[1]), "+f"(d[2]), "+f"(d[3])
        : "r"(a[0]), "r"(a[1]), "r"(a[2]), "r"(a[3]), "r"(b0), "r"(b1));
}
__device__ __forceinline__ void cpasync16(uint32_t dst, const void* src) {
    asm volatile("cp.async.cg.shared.global [%0], [%1], 16;\n"
                 :: "r"(dst), "l"(src));
}
#define CP_COMMIT() asm volatile("cp.async.commit_group;\n" ::)
#define CP_WAIT2()  asm volatile("cp.async.wait_group 2;\n" ::)
#define CP_WAIT1()  asm volatile("cp.async.wait_group 1;\n" ::)

// triple expansion: A side (h,h,l); B side (h,l,h).
__device__ __forceinline__ void tripleA(float v, __nv_bfloat16* o) {
    __nv_bfloat16 h = __float2bfloat16_rn(v);
    __nv_bfloat16 l = __float2bfloat16_rn(v - __bfloat162float(h));
    o[0] = h; o[1] = h; o[2] = l;
}
__device__ __forceinline__ void tripleB(float v, __nv_bfloat16* o) {
    __nv_bfloat16 h = __float2bfloat16_rn(v);
    __nv_bfloat16 l = __float2bfloat16_rn(v - __bfloat162float(h));
    o[0] = h; o[1] = l; o[2] = h;
}
// packed pair-of-triples (two consecutive values -> 3 uint32)
__device__ __forceinline__ void packA2(float v0, float v1, uint32_t u[3]) {
    __nv_bfloat16 h0 = __float2bfloat16_rn(v0);
    __nv_bfloat16 l0 = __float2bfloat16_rn(v0 - __bfloat162float(h0));
    __nv_bfloat16 h1 = __float2bfloat16_rn(v1);
    __nv_bfloat16 l1 = __float2bfloat16_rn(v1 - __bfloat162float(h1));
    uint32_t H0 = __bfloat16_as_ushort(h0), L0 = __bfloat16_as_ushort(l0);
    uint32_t H1 = __bfloat16_as_ushort(h1), L1 = __bfloat16_as_ushort(l1);
    u[0] = H0 | (H0 << 16); u[1] = L0 | (H1 << 16); u[2] = H1 | (L1 << 16);
}
__device__ __forceinline__ void packB2(float v0, float v1, uint32_t u[3]) {
    __nv_bfloat16 h0 = __float2bfloat16_rn(v0);
    __nv_bfloat16 l0 = __float2bfloat16_rn(v0 - __bfloat162float(h0));
    __nv_bfloat16 h1 = __float2bfloat16_rn(v1);
    __nv_bfloat16 l1 = __float2bfloat16_rn(v1 - __bfloat162float(h1));
    uint32_t H0 = __bfloat16_as_ushort(h0), L0 = __bfloat16_as_ushort(l0);
    uint32_t H1 = __bfloat16_as_ushort(h1), L1 = __bfloat16_as_ushort(l1);
    u[0] = H0 | (L0 << 16); u[1] = H0 | (H1 << 16); u[2] = L1 | (H1 << 16);
}

// ---------------- GEMM geometry ----------------
#define KC      32
#define NCHUNK  (KP / KC)           // 72
#define ROWB    80
#define STAGE_A (128 * ROWB)
#define STAGE_B (2 * STAGE_A)
#define SMEM_G  (4 * STAGE_B)       // 81920 B

__device__ __forceinline__ void g_issue(uint32_t smu, int tid, int c,
                                        const __nv_bfloat16* Arows,
                                        const __nv_bfloat16* Brows)
{
    const uint32_t base = smu + (uint32_t)(c & 3) * STAGE_B;
    const int k0 = c * KC;
    #pragma unroll
    for (int r = 0; r < 2; ++r) {
        int idx = tid + r * 256;
        int row = idx >> 2, c16 = idx & 3;
        cpasync16(base + row * ROWB + c16 * 16,
                  Arows + (size_t)row * KP + k0 + c16 * 8);
        cpasync16(base + STAGE_A + row * ROWB + c16 * 16,
                  Brows + (size_t)row * KP + k0 + c16 * 8);
    }
}

__device__ __forceinline__ void gemm_main(const __nv_bfloat16* Arows,
                                          const __nv_bfloat16* Brows,
                                          char* sm, int tid,
                                          float acc[2][8][4])
{
    const int lane = tid & 31, wid = tid >> 5;
    const int wm = wid & 3, wn = wid >> 2;
    const uint32_t smu = smem_u32(sm);

    g_issue(smu, tid, 0, Arows, Brows); CP_COMMIT();
    g_issue(smu, tid, 1, Arows, Brows); CP_COMMIT();
    g_issue(smu, tid, 2, Arows, Brows); CP_COMMIT();

    const uint32_t faoff = (uint32_t)((wm * 32 + (lane & 15)) * ROWB +
                                      ((lane >> 4) & 1) * 16);
    const uint32_t fboff = (uint32_t)(STAGE_A +
                           (wn * 64 + (lane & 7) + ((lane & 16) >> 1)) * ROWB +
                           (lane & 8) * 2);

    for (int c = 0; c < NCHUNK; ++c) {
        CP_WAIT2();
        __syncthreads();
        if (c + 3 < NCHUNK) g_issue(smu, tid, c + 3, Arows, Brows);
        CP_COMMIT();

        const uint32_t sb = smu + (uint32_t)(c & 3) * STAGE_B;
        const uint32_t fa = sb + faoff;
        const uint32_t fb = sb + fboff;
        #pragma unroll
        for (int k16 = 0; k16 < 2; ++k16) {
            uint32_t a0[4], a1[4];
            ldsm4(a0, fa + k16 * 32);
            ldsm4(a1, fa + 16 * ROWB + k16 * 32);
            #pragma unroll
            for (int np = 0; np < 4; ++np) {
                uint32_t bh[4];
                ldsm4(bh, fb + np * 16 * ROWB + k16 * 32);
                mma_bf16(acc[0][np * 2 + 0], a0, bh[0], bh[1]);
                mma_bf16(acc[0][np * 2 + 1], a0, bh[2], bh[3]);
                mma_bf16(acc[1][np * 2 + 0], a1, bh[0], bh[1]);
                mma_bf16(acc[1][np * 2 + 1], a1, bh[2], bh[3]);
            }
        }
    }
}

// ====================================================================
// conversion kernels
// ====================================================================
__global__ void __launch_bounds__(256)
conv_x(const float* __restrict__ x)
{
    const size_t g = (size_t)blockIdx.x * 256 + threadIdx.x;
    const float* src = x + g * 8;
    uint4 buf4[3];
    __nv_bfloat16* buf = (__nv_bfloat16*)buf4;
    float4 v0 = *(const float4*)(src);
    float4 v1 = *(const float4*)(src + 4);
    tripleA(v0.x, buf + 0);  tripleA(v0.y, buf + 3);
    tripleA(v0.z, buf + 6);  tripleA(v0.w, buf + 9);
    tripleA(v1.x, buf + 12); tripleA(v1.y, buf + 15);
    tripleA(v1.z, buf + 18); tripleA(v1.w, buf + 21);
    uint4* dp = (uint4*)(g_xi + g * 24);
    dp[0] = buf4[0]; dp[1] = buf4[1]; dp[2] = buf4[2];
}

__global__ void __launch_bounds__(256)
conv_w(const float* __restrict__ Wq, const float* __restrict__ Wk,
       const float* __restrict__ Wv)
{
    __shared__ float tile[64][65];
    const int e0  = blockIdx.x * 64;
    const int h   = blockIdx.y;
    const int mat = blockIdx.z;
    const float* W = (mat == 0) ? Wq : (mat == 1) ? Wk : Wv;
    const int tid = threadIdx.x;

    #pragma unroll
    for (int r = 0; r < 16; ++r) {
        int idx = tid + r * 256;
        int el = idx >> 6, d = idx & 63;
        tile[el][d] = W[((size_t)h * E_ + e0 + el) * DH_ + d];
    }
    __syncthreads();

    const int d = tid >> 2, eg = tid & 3;
    uint4 buf4[6];
    __nv_bfloat16* buf = (__nv_bfloat16*)buf4;
    #pragma unroll
    for (int i = 0; i < 16; ++i)
        tripleB(tile[eg * 16 + i][d], buf + 3 * i);
    uint4* dp = (uint4*)(g_wb + ((size_t)mat * DM_ + h * 64 + d) * KP +
                         (size_t)(e0 + eg * 16) * 3);
    #pragma unroll
    for (int j = 0; j < 6; ++j) dp[j] = buf4[j];
}

// V transpose + triple expansion: g_V [bh][s][64] -> g_Vt [bh][d][3s]
__global__ void __launch_bounds__(256)
vtrans()
{
    __shared__ float tile[64][65];
    const int s0 = blockIdx.x * 64;
    const int bh = blockIdx.y;
    const int tid = threadIdx.x;

    #pragma unroll
    for (int r = 0; r < 16; ++r) {
        int idx = tid + r * 256;
        int s = idx >> 6, d = idx & 63;
        tile[s][d] = g_V[((size_t)bh * S_ + s0 + s) * DH_ + d];
    }
    __syncthreads();

    const int d = tid >> 2, sg = tid & 3;
    uint4 buf4[6];
    __nv_bfloat16* buf = (__nv_bfloat16*)buf4;
    #pragma unroll
    for (int i = 0; i < 16; ++i)
        tripleB(tile[sg * 16 + i][d], buf + 3 * i);
    uint4* dp = (uint4*)(g_Vt + ((size_t)bh * DH_ + d) * (3 * S_) +
                         (size_t)(s0 + sg * 16) * 3);
    #pragma unroll
    for (int j = 0; j < 6; ++j) dp[j] = buf4[j];
}

// ====================================================================
// K1: QKV projection (z = 0,1,2) + folded conv_wd blocks (z = 3).
// Epilogue: Q -> g_Qi (A-triples), K -> g_Ki (B-triples), V -> g_V fp32.
// ====================================================================
__global__ void __launch_bounds__(256, 2)
qkv_mma(const float* __restrict__ bq, const float* __restrict__ bk,
        const float* __restrict__ bv, const float* __restrict__ Wd)
{
    extern __shared__ char sm[];
    const int tid = threadIdx.x, lane = tid & 31, wid = tid >> 5;
    const int wm = wid & 3, wn = wid >> 2;

    const int mat = blockIdx.z;
    if (mat == 3) {
        // folded conv_wd: Wd[k][n] -> g_wdb[n][3k..] (B order)
        const int idx = blockIdx.y * 32 + blockIdx.x;
        if (idx >= 144) return;
        __shared__ float tile[64][65];
        const int k0 = (idx / 12) * 64;
        const int n0 = (idx % 12) * 64;
        #pragma unroll
        for (int r = 0; r < 16; ++r) {
            int ii = tid + r * 256;
            int kl = ii >> 6, nl = ii & 63;
            tile[kl][nl] = Wd[(size_t)(k0 + kl) * DM_ + n0 + nl];
        }
        __syncthreads();
        const int nl = tid >> 2, kg = tid & 3;
        uint4 buf4[6];
        __nv_bfloat16* buf = (__nv_bfloat16*)buf4;
        #pragma unroll
        for (int i = 0; i < 16; ++i)
            tripleB(tile[kg * 16 + i][nl], buf + 3 * i);
        uint4* dp = (uint4*)(g_wdb + (size_t)(n0 + nl) * KP +
                             (size_t)(k0 + kg * 16) * 3);
        #pragma unroll
        for (int j = 0; j < 6; ++j) dp[j] = buf4[j];
        return;
    }

    const float* bias = (mat == 0) ? bq : (mat == 1) ? bk : bv;

    const int t0 = blockIdx.x * 128;
    const int n0 = blockIdx.y * 128;

    float acc[2][8][4];
    #pragma unroll
    for (int i = 0; i < 2; ++i)
        #pragma unroll
        for (int j = 0; j < 8; ++j)
            #pragma unroll
            for (int k = 0; k < 4; ++k) acc[i][j][k] = 0.f;

    gemm_main(g_xi + (size_t)t0 * KP,
              g_wb + ((size_t)mat * DM_ + n0) * KP, sm, tid, acc);

    #pragma unroll
    for (int mi = 0; mi < 2; ++mi) {
        #pragma unroll
        for (int ni = 0; ni < 8; ++ni) {
            const int cl = wn * 64 + ni * 8 + (lane & 3) * 2;
            const int ng = n0 + cl;
            const int h = ng >> 6, d = ng & 63;
            const float b0v = bias[h * DH_ + d];
            const float b1v = bias[h * DH_ + d + 1];
            #pragma unroll
            for (int r8 = 0; r8 < 2; ++r8) {
                const int t = t0 + wm * 32 + mi * 16 + (lane >> 2) + r8 * 8;
                const int bb = t >> 10, ss = t & (S_ - 1);
                const float v0 = acc[mi][ni][2 * r8] + b0v;
                const float v1 = acc[mi][ni][2 * r8 + 1] + b1v;
                if (mat == 0) {
                    uint32_t u[3];
                    packA2(v0, v1, u);
                    uint32_t* dp = (uint32_t*)(g_Qi +
                        ((size_t)(bb * H_ + h) * S_ + ss) * KH + d * 3);
                    dp[0] = u[0]; dp[1] = u[1]; dp[2] = u[2];
                } else if (mat == 1) {
                    uint32_t u[3];
                    packB2(v0, v1, u);
                    uint32_t* dp = (uint32_t*)(g_Ki +
                        ((size_t)(bb * H_ + h) * S_ + ss) * KH + d * 3);
                    dp[0] = u[0]; dp[1] = u[1]; dp[2] = u[2];
                } else {
                    *(float2*)(g_V + ((size_t)(bb * H_ + h) * S_ + ss) * DH_ + d)
                        = make_float2(v0, v1);
                }
            }
        }
    }
}

// ====================================================================
// K4: output dense (blocks < 192) + fused normw sweep (blocks >= 192).
// grid 448, block 256, smem SMEM_G (dense path only).
// ====================================================================
__global__ void __launch_bounds__(256, 2)
dense_normw(const float* __restrict__ bd, float* __restrict__ out)
{
    const int tid = threadIdx.x;

    if (blockIdx.x >= 192) {
        // ---- normw: exp-normalize the score region of d_out ----
        const int nb = blockIdx.x - 192;          // 0..255
        for (int r = 0; r < 192; ++r) {
            const int row = nb * 192 + r;         // (b*S + s)*H + h
            const int h  = row % H_;
            const int bs = row / H_;
            const int s  = bs & (S_ - 1);
            const int b  = bs >> 10;
            const float m    = g_m[(b * H_ + h) * S_ + s];
            const float invl = 1.0f / g_l[(b * H_ + h) * S_ + s];
            size_t base = (size_t)row * S_ + tid * 4;
            float4 p = *(float4*)(out + base);
            p.x = __expf(p.x - m) * invl;
            p.y = __expf(p.y - m) * invl;
            p.z = __expf(p.z - m) * invl;
            p.w = __expf(p.w - m) * invl;
            *(float4*)(out + base) = p;
        }
        return;
    }

    // ---- dense GEMM ----
    extern __shared__ char sm[];
    const int lane = tid & 31, wid = tid >> 5;
    const int wm = wid & 3, wn = wid >> 2;

    const int t0 = (blockIdx.x & 31) * 128;
    const int n0 = (blockIdx.x >> 5) * 128;

    float acc[2][8][4];
    #pragma unroll
    for (int i = 0; i < 2; ++i)
        #pragma unroll
        for (int j = 0; j < 8; ++j)
            #pragma unroll
            for (int k = 0; k < 4; ++k) acc[i][j][k] = 0.f;

    gemm_main(g_ai + (size_t)t0 * KP, g_wdb + (size_t)n0 * KP, sm, tid, acc);

    #pragma unroll
    for (int mi = 0; mi < 2; ++mi) {
        #pragma unroll
        for (int ni = 0; ni < 8; ++ni) {
            const int cl = wn * 64 + ni * 8 + (lane & 3) * 2;
            const float b0v = bd[n0 + cl];
            const float b1v = bd[n0 + cl + 1];
            #pragma unroll
            for (int r8 = 0; r8 < 2; ++r8) {
                const int t = t0 + wm * 32 + mi * 16 + (lane >> 2) + r8 * 8;
                float2 o = make_float2(acc[mi][ni][2 * r8] + b0v,
                                       acc[mi][ni][2 * r8 + 1] + b1v);
                *(float2*)(g_y + (size_t)t * DM_ + n0 + cl) = o;
            }
        }
    }
}

// ====================================================================
// K2: attention on mma.sync with split-3 triples.
// grid (8, 12, 4), block 256 (8 warps x 16 q-rows), smem 204800 B.
// ====================================================================
#define ASTR   400
#define QS_OFF 0u
#define KS_OFF 51200u
#define VS_OFF 102400u
#define PS_OFF 153600u
#define SMEM_ATT 204800

__device__ __forceinline__ void attn_issue(uint32_t smu, int tid, int kt,
                                           const __nv_bfloat16* Ki_h,
                                           const __nv_bfloat16* Vt_h)
{
    if (kt >= 16) return;
    const uint32_t kb = smu + KS_OFF + (uint32_t)(kt & 1) * 25600u;
    const uint32_t vb = smu + VS_OFF + (uint32_t)(kt & 1) * 25600u;
    #pragma unroll
    for (int r = 0; r < 6; ++r) {
        int idx = tid + r * 256;
        int row = idx / 24, col = idx - row * 24;
        cpasync16(kb + row * ASTR + col * 16,
                  Ki_h + ((size_t)(kt * 64 + row)) * KH + col * 8);
        cpasync16(vb + row * ASTR + col * 16,
                  Vt_h + (size_t)row * (3 * S_) + kt * 192 + col * 8);
    }
}

__global__ void __launch_bounds__(256)
attn_mma(float* __restrict__ out)
{
    extern __shared__ char sm[];
    const int tid = threadIdx.x, lane = tid & 31, wid = tid >> 5;
    const int b = blockIdx.z, h = blockIdx.y;
    const int q0 = blockIdx.x * 128;
    const int bh = b * H_ + h;
    const __nv_bfloat16* Qi_h = g_Qi + (size_t)bh * S_ * KH;
    const __nv_bfloat16* Ki_h = g_Ki + (size_t)bh * S_ * KH;
    const __nv_bfloat16* Vt_h = g_Vt + (size_t)bh * DH_ * (3 * S_);
    const uint32_t smu = smem_u32(sm);

    #pragma unroll
    for (int r = 0; r < 12; ++r) {
        int idx = tid + r * 256;
        int row = idx / 24, col = idx - row * 24;
        cpasync16(smu + QS_OFF + row * ASTR + col * 16,
                  Qi_h + (size_t)(q0 + row) * KH + col * 8);
    }
    attn_issue(smu, tid, 0, Ki_h, Vt_h);
    CP_COMMIT();
    attn_issue(smu, tid, 1, Ki_h, Vt_h);
    CP_COMMIT();

    const uint32_t faoff = (uint32_t)((wid * 16 + (lane & 15)) * ASTR +
                                      ((lane >> 4) & 1) * 16);
    const uint32_t fboff = (uint32_t)(((lane & 7) + ((lane & 16) >> 1)) * ASTR +
                                      (lane & 8) * 2);

    float ctx[8][4];
    #pragma unroll
    for (int i = 0; i < 8; ++i)
        #pragma unroll
        for (int j = 0; j < 4; ++j) ctx[i][j] = 0.f;
    float m0 = -1e30f, m1 = -1e30f, l0 = 0.f, l1 = 0.f;

    const int r0 = lane >> 2;
    const int srow0 = q0 + wid * 16 + r0;       // rows srow0 and srow0+8
    float* orow0 = out + ((size_t)(b * S_ + srow0) * H_ + h) * S_;
    float* orow1 = out + ((size_t)(b * S_ + srow0 + 8) * H_ + h) * S_;

    for (int kt = 0; kt < 16; ++kt) {
        CP_WAIT1();
        __syncthreads();

        const uint32_t kb = smu + KS_OFF + (uint32_t)(kt & 1) * 25600u;
        const uint32_t vb = smu + VS_OFF + (uint32_t)(kt & 1) * 25600u;

        // ---- QK^T over k''=192 ----
        float p[8][4];
        #pragma unroll
        for (int i = 0; i < 8; ++i)
            #pragma unroll
            for (int j = 0; j < 4; ++j) p[i][j] = 0.f;
        #pragma unroll
        for (int k16 = 0; k16 < 12; ++k16) {
            uint32_t a[4];
            ldsm4(a, smu + QS_OFF + faoff + k16 * 32);
            #pragma unroll
            for (int np = 0; np < 4; ++np) {
                uint32_t bv[4];
                ldsm4(bv, kb + fboff + np * 16 * ASTR + k16 * 32);
                mma_bf16(p[np * 2 + 0], a, bv[0], bv[1]);
                mma_bf16(p[np * 2 + 1], a, bv[2], bv[3]);
            }
        }

        // ---- scale + write raw scores ----
        #pragma unroll
        for (int ni = 0; ni < 8; ++ni) {
            #pragma unroll
            for (int j = 0; j < 4; ++j) p[ni][j] *= SQK;
            const int c = kt * 64 + ni * 8 + (lane & 3) * 2;
            *(float2*)(orow0 + c) = make_float2(p[ni][0], p[ni][1]);
            *(float2*)(orow1 + c) = make_float2(p[ni][2], p[ni][3]);
        }

        // ---- online softmax; P-triples into Ps (warp-private rows) ----
        float mx0 = -1e30f, mx1 = -1e30f;
        #pragma unroll
        for (int ni = 0; ni < 8; ++ni) {
            mx0 = fmaxf(mx0, fmaxf(p[ni][0], p[ni][1]));
            mx1 = fmaxf(mx1, fmaxf(p[ni][2], p[ni][3]));
        }
        mx0 = fmaxf(mx0, __shfl_xor_sync(0xffffffffu, mx0, 1));
        mx0 = fmaxf(mx0, __shfl_xor_sync(0xffffffffu, mx0, 2));
        mx1 = fmaxf(mx1, __shfl_xor_sync(0xffffffffu, mx1, 1));
        mx1 = fmaxf(mx1, __shfl_xor_sync(0xffffffffu, mx1, 2));
        const float mn0 = fmaxf(m0, mx0), mn1 = fmaxf(m1, mx1);
        const float f0 = __expf(m0 - mn0), f1 = __expf(m1 - mn1);
        m0 = mn0; m1 = mn1;

        float s0 = 0.f, s1 = 0.f;
        const uint32_t psrow0 = smu + PS_OFF + (wid * 16 + r0) * ASTR;
        const uint32_t psrow1 = psrow0 + 8 * ASTR;
        #pragma unroll
        for (int ni = 0; ni < 8; ++ni) {
            const float e0 = __expf(p[ni][0] - mn0);
            const float e1 = __expf(p[ni][1] - mn0);
            const float e2 = __expf(p[ni][2] - mn1);
            const float e3 = __expf(p[ni][3] - mn1);
            s0 += e0 + e1; s1 += e2 + e3;
            const int cb = (ni * 8 + (lane & 3) * 2) * 6;   // byte offset 6*c
            uint32_t u[3];
            packA2(e0, e1, u);
            *(uint32_t*)(sm + (psrow0 - smu) + cb + 0) = u[0];
            *(uint32_t*)(sm + (psrow0 - smu) + cb + 4) = u[1];
            *(uint32_t*)(sm + (psrow0 - smu) + cb + 8) = u[2];
            packA2(e2, e3, u);
            *(uint32_t*)(sm + (psrow1 - smu) + cb + 0) = u[0];
            *(uint32_t*)(sm + (psrow1 - smu) + cb + 4) = u[1];
            *(uint32_t*)(sm + (psrow1 - smu) + cb + 8) = u[2];
        }
        s0 += __shfl_xor_sync(0xffffffffu, s0, 1);
        s0 += __shfl_xor_sync(0xffffffffu, s0, 2);
        s1 += __shfl_xor_sync(0xffffffffu, s1, 1);
        s1 += __shfl_xor_sync(0xffffffffu, s1, 2);
        l0 = l0 * f0 + s0;
        l1 = l1 * f1 + s1;
        #pragma unroll
        for (int ni = 0; ni < 8; ++ni) {
            ctx[ni][0] *= f0; ctx[ni][1] *= f0;
            ctx[ni][2] *= f1; ctx[ni][3] *= f1;
        }
        __syncwarp();   // Ps rows are warp-private; warp-level fence suffices

        // ---- PV over n''=192 ----
        #pragma unroll
        for (int k16 = 0; k16 < 12; ++k16) {
            uint32_t a[4];
            ldsm4(a, smu + PS_OFF + faoff + k16 * 32);
            #pragma unroll
            for (int np = 0; np < 4; ++np) {
                uint32_t bv[4];
                ldsm4(bv, vb + fboff + np * 16 * ASTR + k16 * 32);
                mma_bf16(ctx[np * 2 + 0], a, bv[0], bv[1]);
                mma_bf16(ctx[np * 2 + 1], a, bv[2], bv[3]);
            }
        }
        __syncthreads();   // all warps done with Ks/Vs this stage

        attn_issue(smu, tid, kt + 2, Ki_h, Vt_h);
        CP_COMMIT();
    }

    // ---- epilogue: ctx/l -> A-triples into g_ai; store m,l ----
    const float inv0 = 1.f / l0, inv1 = 1.f / l1;
    const int t0row = b * S_ + srow0;
    #pragma unroll
    for (int ni = 0; ni < 8; ++ni) {
        const int d = ni * 8 + (lane & 3) * 2;
        uint32_t u[3];
        packA2(ctx[ni][0] * inv0, ctx[ni][1] * inv0, u);
        uint32_t* dp = (uint32_t*)(g_ai + (size_t)t0row * KP + (h * 64 + d) * 3);
        dp[0] = u[0]; dp[1] = u[1]; dp[2] = u[2];
        packA2(ctx[ni][2] * inv1, ctx[ni][3] * inv1, u);
        dp = (uint32_t*)(g_ai + (size_t)(t0row + 8) * KP + (h * 64 + d) * 3);
        dp[0] = u[0]; dp[1] = u[1]; dp[2] = u[2];
    }
    if ((lane & 3) == 0) {
        g_m[(size_t)bh * S_ + srow0] = m0;
        g_l[(size_t)bh * S_ + srow0] = l0;
        g_m[(size_t)bh * S_ + srow0 + 8] = m1;
        g_l[(size_t)bh * S_ + srow0 + 8] = l1;
    }
}

// ====================================================================
// K5: LayerNorm. grid T, block 256.
// ====================================================================
__global__ void __launch_bounds__(256)
ln_kernel(const float* __restrict__ gamma, const float* __restrict__ beta,
          float* __restrict__ out)
{
    __shared__ float row[DM_];
    __shared__ float red[8];

    const int t = blockIdx.x;
    const int tid = threadIdx.x;

    float s = 0.f;
    #pragma unroll
    for (int j = 0; j < 3; j++) {
        float v = g_y[(size_t)t * DM_ + tid + j * 256];
        row[tid + j * 256] = v;
        s += v;
    }
    #pragma unroll
    for (int o = 16; o > 0; o >>= 1) s += __shfl_xor_sync(0xffffffffu, s, o);
    if ((tid & 31) == 0) red[tid >> 5] = s;
    __syncthreads();
    float tot = red[0];
    #pragma unroll
    for (int i = 1; i < 8; i++) tot += red[i];
    const float mu = tot * (1.0f / DM_);
    __syncthreads();

    float vs = 0.f;
    #pragma unroll
    for (int j = 0; j < 3; j++) {
        float d = row[tid + j * 256] - mu;
        vs += d * d;
    }
    #pragma unroll
    for (int o = 16; o > 0; o >>= 1) vs += __shfl_xor_sync(0xffffffffu, vs, o);
    if ((tid & 31) == 0) red[tid >> 5] = vs;
    __syncthreads();
    float tv = red[0];
    #pragma unroll
    for (int i = 1; i < 8; i++) tv += red[i];
    const float scale = rsqrtf(tv * (1.0f / DM_) + 1e-12f);

    #pragma unroll
    for (int j = 0; j < 3; j++) {
        const int idx = tid + j * 256;
        out[WOFF + (size_t)t * DM_ + idx] =
            (row[idx] - mu) * scale * gamma[idx] + beta[idx];
    }
}

// ====================================================================
// launch
// ====================================================================
extern "C" void kernel_launch(void* const* d_in, const int* in_sizes, int n_in,
                              void* d_out, int out_size)
{
    (void)in_sizes; (void)n_in; (void)out_size;
    const float* x     = (const float*)d_in[0];
    const float* Wq    = (const float*)d_in[1];
    const float* bq    = (const float*)d_in[2];
    const float* Wk    = (const float*)d_in[3];
    const float* bk    = (const float*)d_in[4];
    const float* Wv    = (const float*)d_in[5];
    const float* bv    = (const float*)d_in[6];
    const float* Wd    = (const float*)d_in[7];
    const float* bd    = (const float*)d_in[8];
    const float* gamma = (const float*)d_in[9];
    const float* beta  = (const float*)d_in[10];
    float* out = (float*)d_out;

    cudaFuncSetAttribute(qkv_mma,
                         cudaFuncAttributeMaxDynamicSharedMemorySize, SMEM_G);
    cudaFuncSetAttribute(dense_normw,
                         cudaFuncAttributeMaxDynamicSharedMemorySize, SMEM_G);
    cudaFuncSetAttribute(attn_mma,
                         cudaFuncAttributeMaxDynamicSharedMemorySize, SMEM_ATT);

    conv_x<<<T_ * E_ / 8 / 256, 256>>>(x);
    conv_w<<<dim3(E_ / 64, H_, 3), 256>>>(Wq, Wk, Wv);

    // z = 0,1,2: Q/K/V GEMMs; z = 3: folded conv_wd blocks
    qkv_mma<<<dim3(T_ / 128, DM_ / 128, 4), 256, SMEM_G>>>(bq, bk, bv, Wd);

    vtrans<<<dim3(S_ / 64, B_ * H_), 256>>>();

    attn_mma<<<dim3(S_ / 128, H_, B_), 256, SMEM_ATT>>>(out);

    // blocks 0..191: dense GEMM; blocks 192..447: normw sweep (overlapped)
    dense_normw<<<448, 256, SMEM_G>>>(bd, out);

    ln_kernel<<<T_, 256>>>(gamma, beta, out);
}

// round 14
// speedup vs baseline: 1.1083x; 1.1083x over previous
#include <cuda_runtime.h>
#include <cuda_bf16.h>
#include <cstdint>
#include <cstddef>

// ---------------- problem constants ----------------
#define B_   4
#define S_   1024
#define H_   12
#define DH_  64
#define E_   768
#define DM_  768
#define T_   (B_ * S_)            // 4096 tokens
#define KP   2304                 // triple-expanded K for the big GEMMs
#define KH   192                  // triple-expanded head dim (3*64)
#define SQK  0.125f               // 1/sqrt(64)
#define WOFF ((size_t)B_ * S_ * H_ * S_)   // start of y in d_out

// ---------------- scratch (device globals; no allocation) ----------------
__device__ float g_y [T_ * DM_];
__device__ float g_m [B_ * H_ * S_];
__device__ float g_l [B_ * H_ * S_];
__device__ float g_V [B_ * H_ * S_ * DH_];          // V fp32 [bh][s][64]
// triple-expanded bf16 operands
__device__ __nv_bfloat16 g_xi [T_ * KP];            // x tokens (A order)
__device__ __nv_bfloat16 g_ai [T_ * KP];            // ctx tokens (A order)
__device__ __nv_bfloat16 g_wb [3 * DM_ * KP];       // qkv weights (B order)
__device__ __nv_bfloat16 g_wdb[DM_ * KP];           // dense weights (B order)
// attention operands
__device__ __nv_bfloat16 g_Qi [B_ * H_ * S_ * KH];  // Q A-triples [bh][s][192]
__device__ __nv_bfloat16 g_Ki [B_ * H_ * S_ * KH];  // K B-triples [bh][s][192]
__device__ __nv_bfloat16 g_Vt [B_ * H_ * DH_ * 3 * S_]; // V B-triples [bh][d][3s]

// ---------------- mma.sync / ldmatrix / cp.async helpers ----------------
typedef unsigned long long ull;

__device__ __forceinline__ uint32_t smem_u32(const void* p) {
    uint32_t a;
    asm("{ .reg .u64 t; cvta.to.shared.u64 t, %1; cvt.u32.u64 %0, t; }"
        : "=r"(a) : "l"(p));
    return a;
}
__device__ __forceinline__ void ldsm4(uint32_t r[4], uint32_t addr) {
    asm volatile("ldmatrix.sync.aligned.m8n8.x4.shared.b16 {%0,%1,%2,%3}, [%4];"
                 : "=r"(r[0]), "=r"(r[1]), "=r"(r[2]), "=r"(r[3]) : "r"(addr));
}
__device__ __forceinline__ void mma_bf16(float d[4], const uint32_t a[4],
                                         uint32_t b0, uint32_t b1) {
    asm volatile(
        "mma.sync.aligned.m16n8k16.row.col.f32.bf16.bf16.f32 "
        "{%0,%1,%2,%3}, {%4,%5,%6,%7}, {%8,%9}, {%0,%1,%2,%3};"
        : "+f"(d[0]), "+f"(d[1]), "+f"(d[2]), "+f"(d[3])
        : "r"(a[0]), "r"(a[1]), "r"(a[2]), "r"(a[3]), "r"(b0), "r"(b1));
}
__device__ __forceinline__ void cpasync16(uint32_t dst, const void* src) {
    asm volatile("cp.async.cg.shared.global [%0], [%1], 16;\n"
                 :: "r"(dst), "l"(src));
}
#define CP_COMMIT() asm volatile("cp.async.commit_group;\n" ::)
#define CP_WAIT2()  asm volatile("cp.async.wait_group 2;\n" ::)
#define CP_WAIT1()  asm volatile("cp.async.wait_group 1;\n" ::)

// triple expansion: A side (h,h,l); B side (h,l,h).
__device__ __forceinline__ void tripleA(float v, __nv_bfloat16* o) {
    __nv_bfloat16 h = __float2bfloat16_rn(v);
    __nv_bfloat16 l = __float2bfloat16_rn(v - __bfloat162float(h));
    o[0] = h; o[1] = h; o[2] = l;
}
__device__ __forceinline__ void tripleB(float v, __nv_bfloat16* o) {
    __nv_bfloat16 h = __float2bfloat16_rn(v);
    __nv_bfloat16 l = __float2bfloat16_rn(v - __bfloat162float(h));
    o[0] = h; o[1] = l; o[2] = h;
}
// packed pair-of-triples (two consecutive values -> 3 uint32)
__device__ __forceinline__ void packA2(float v0, float v1, uint32_t u[3]) {
    __nv_bfloat16 h0 = __float2bfloat16_rn(v0);
    __nv_bfloat16 l0 = __float2bfloat16_rn(v0 - __bfloat162float(h0));
    __nv_bfloat16 h1 = __float2bfloat16_rn(v1);
    __nv_bfloat16 l1 = __float2bfloat16_rn(v1 - __bfloat162float(h1));
    uint32_t H0 = __bfloat16_as_ushort(h0), L0 = __bfloat16_as_ushort(l0);
    uint32_t H1 = __bfloat16_as_ushort(h1), L1 = __bfloat16_as_ushort(l1);
    u[0] = H0 | (H0 << 16); u[1] = L0 | (H1 << 16); u[2] = H1 | (L1 << 16);
}
__device__ __forceinline__ void packB2(float v0, float v1, uint32_t u[3]) {
    __nv_bfloat16 h0 = __float2bfloat16_rn(v0);
    __nv_bfloat16 l0 = __float2bfloat16_rn(v0 - __bfloat162float(h0));
    __nv_bfloat16 h1 = __float2bfloat16_rn(v1);
    __nv_bfloat16 l1 = __float2bfloat16_rn(v1 - __bfloat162float(h1));
    uint32_t H0 = __bfloat16_as_ushort(h0), L0 = __bfloat16_as_ushort(l0);
    uint32_t H1 = __bfloat16_as_ushort(h1), L1 = __bfloat16_as_ushort(l1);
    u[0] = H0 | (L0 << 16); u[1] = H0 | (H1 << 16); u[2] = L1 | (H1 << 16);
}

// ---------------- GEMM geometry ----------------
#define KC      32
#define NCHUNK  (KP / KC)           // 72
#define ROWB    80
#define STAGE_A (128 * ROWB)
#define STAGE_B (2 * STAGE_A)
#define SMEM_G  (4 * STAGE_B)       // 81920 B

__device__ __forceinline__ void g_issue(uint32_t smu, int tid, int c,
                                        const __nv_bfloat16* Arows,
                                        const __nv_bfloat16* Brows)
{
    const uint32_t base = smu + (uint32_t)(c & 3) * STAGE_B;
    const int k0 = c * KC;
    #pragma unroll
    for (int r = 0; r < 2; ++r) {
        int idx = tid + r * 256;
        int row = idx >> 2, c16 = idx & 3;
        cpasync16(base + row * ROWB + c16 * 16,
                  Arows + (size_t)row * KP + k0 + c16 * 8);
        cpasync16(base + STAGE_A + row * ROWB + c16 * 16,
                  Brows + (size_t)row * KP + k0 + c16 * 8);
    }
}

__device__ __forceinline__ void gemm_main(const __nv_bfloat16* Arows,
                                          const __nv_bfloat16* Brows,
                                          char* sm, int tid,
                                          float acc[2][8][4])
{
    const int lane = tid & 31, wid = tid >> 5;
    const int wm = wid & 3, wn = wid >> 2;
    const uint32_t smu = smem_u32(sm);

    g_issue(smu, tid, 0, Arows, Brows); CP_COMMIT();
    g_issue(smu, tid, 1, Arows, Brows); CP_COMMIT();
    g_issue(smu, tid, 2, Arows, Brows); CP_COMMIT();

    const uint32_t faoff = (uint32_t)((wm * 32 + (lane & 15)) * ROWB +
                                      ((lane >> 4) & 1) * 16);
    const uint32_t fboff = (uint32_t)(STAGE_A +
                           (wn * 64 + (lane & 7) + ((lane & 16) >> 1)) * ROWB +
                           (lane & 8) * 2);

    for (int c = 0; c < NCHUNK; ++c) {
        CP_WAIT2();
        __syncthreads();
        if (c + 3 < NCHUNK) g_issue(smu, tid, c + 3, Arows, Brows);
        CP_COMMIT();

        const uint32_t sb = smu + (uint32_t)(c & 3) * STAGE_B;
        const uint32_t fa = sb + faoff;
        const uint32_t fb = sb + fboff;
        #pragma unroll
        for (int k16 = 0; k16 < 2; ++k16) {
            uint32_t a0[4], a1[4];
            ldsm4(a0, fa + k16 * 32);
            ldsm4(a1, fa + 16 * ROWB + k16 * 32);
            #pragma unroll
            for (int np = 0; np < 4; ++np) {
                uint32_t bh[4];
                ldsm4(bh, fb + np * 16 * ROWB + k16 * 32);
                mma_bf16(acc[0][np * 2 + 0], a0, bh[0], bh[1]);
                mma_bf16(acc[0][np * 2 + 1], a0, bh[2], bh[3]);
                mma_bf16(acc[1][np * 2 + 0], a1, bh[0], bh[1]);
                mma_bf16(acc[1][np * 2 + 1], a1, bh[2], bh[3]);
            }
        }
    }
}

// ====================================================================
// conversion kernels
// ====================================================================
__global__ void __launch_bounds__(256)
conv_x(const float* __restrict__ x)
{
    const size_t g = (size_t)blockIdx.x * 256 + threadIdx.x;
    const float* src = x + g * 8;
    uint4 buf4[3];
    __nv_bfloat16* buf = (__nv_bfloat16*)buf4;
    float4 v0 = *(const float4*)(src);
    float4 v1 = *(const float4*)(src + 4);
    tripleA(v0.x, buf + 0);  tripleA(v0.y, buf + 3);
    tripleA(v0.z, buf + 6);  tripleA(v0.w, buf + 9);
    tripleA(v1.x, buf + 12); tripleA(v1.y, buf + 15);
    tripleA(v1.z, buf + 18); tripleA(v1.w, buf + 21);
    uint4* dp = (uint4*)(g_xi + g * 24);
    dp[0] = buf4[0]; dp[1] = buf4[1]; dp[2] = buf4[2];
}

__global__ void __launch_bounds__(256)
conv_w(const float* __restrict__ Wq, const float* __restrict__ Wk,
       const float* __restrict__ Wv)
{
    __shared__ float tile[64][65];
    const int e0  = blockIdx.x * 64;
    const int h   = blockIdx.y;
    const int mat = blockIdx.z;
    const float* W = (mat == 0) ? Wq : (mat == 1) ? Wk : Wv;
    const int tid = threadIdx.x;

    #pragma unroll
    for (int r = 0; r < 16; ++r) {
        int idx = tid + r * 256;
        int el = idx >> 6, d = idx & 63;
        tile[el][d] = W[((size_t)h * E_ + e0 + el) * DH_ + d];
    }
    __syncthreads();

    const int d = tid >> 2, eg = tid & 3;
    uint4 buf4[6];
    __nv_bfloat16* buf = (__nv_bfloat16*)buf4;
    #pragma unroll
    for (int i = 0; i < 16; ++i)
        tripleB(tile[eg * 16 + i][d], buf + 3 * i);
    uint4* dp = (uint4*)(g_wb + ((size_t)mat * DM_ + h * 64 + d) * KP +
                         (size_t)(e0 + eg * 16) * 3);
    #pragma unroll
    for (int j = 0; j < 6; ++j) dp[j] = buf4[j];
}

// V transpose + triple expansion: g_V [bh][s][64] -> g_Vt [bh][d][3s]
__global__ void __launch_bounds__(256)
vtrans()
{
    __shared__ float tile[64][65];
    const int s0 = blockIdx.x * 64;
    const int bh = blockIdx.y;
    const int tid = threadIdx.x;

    #pragma unroll
    for (int r = 0; r < 16; ++r) {
        int idx = tid + r * 256;
        int s = idx >> 6, d = idx & 63;
        tile[s][d] = g_V[((size_t)bh * S_ + s0 + s) * DH_ + d];
    }
    __syncthreads();

    const int d = tid >> 2, sg = tid & 3;
    uint4 buf4[6];
    __nv_bfloat16* buf = (__nv_bfloat16*)buf4;
    #pragma unroll
    for (int i = 0; i < 16; ++i)
        tripleB(tile[sg * 16 + i][d], buf + 3 * i);
    uint4* dp = (uint4*)(g_Vt + ((size_t)bh * DH_ + d) * (3 * S_) +
                         (size_t)(s0 + sg * 16) * 3);
    #pragma unroll
    for (int j = 0; j < 6; ++j) dp[j] = buf4[j];
}

// ====================================================================
// K1: QKV projection (z = 0,1,2) + folded conv_wd blocks (z = 3).
// Epilogue: Q -> g_Qi (A-triples), K -> g_Ki (B-triples), V -> g_V fp32.
// ====================================================================
__global__ void __launch_bounds__(256, 2)
qkv_mma(const float* __restrict__ bq, const float* __restrict__ bk,
        const float* __restrict__ bv, const float* __restrict__ Wd)
{
    extern __shared__ char sm[];
    const int tid = threadIdx.x, lane = tid & 31, wid = tid >> 5;
    const int wm = wid & 3, wn = wid >> 2;

    const int mat = blockIdx.z;
    if (mat == 3) {
        // folded conv_wd: Wd[k][n] -> g_wdb[n][3k..] (B order)
        const int idx = blockIdx.y * 32 + blockIdx.x;
        if (idx >= 144) return;
        __shared__ float tile[64][65];
        const int k0 = (idx / 12) * 64;
        const int n0 = (idx % 12) * 64;
        #pragma unroll
        for (int r = 0; r < 16; ++r) {
            int ii = tid + r * 256;
            int kl = ii >> 6, nl = ii & 63;
            tile[kl][nl] = Wd[(size_t)(k0 + kl) * DM_ + n0 + nl];
        }
        __syncthreads();
        const int nl = tid >> 2, kg = tid & 3;
        uint4 buf4[6];
        __nv_bfloat16* buf = (__nv_bfloat16*)buf4;
        #pragma unroll
        for (int i = 0; i < 16; ++i)
            tripleB(tile[kg * 16 + i][nl], buf + 3 * i);
        uint4* dp = (uint4*)(g_wdb + (size_t)(n0 + nl) * KP +
                             (size_t)(k0 + kg * 16) * 3);
        #pragma unroll
        for (int j = 0; j < 6; ++j) dp[j] = buf4[j];
        return;
    }

    const float* bias = (mat == 0) ? bq : (mat == 1) ? bk : bv;

    const int t0 = blockIdx.x * 128;
    const int n0 = blockIdx.y * 128;

    float acc[2][8][4];
    #pragma unroll
    for (int i = 0; i < 2; ++i)
        #pragma unroll
        for (int j = 0; j < 8; ++j)
            #pragma unroll
            for (int k = 0; k < 4; ++k) acc[i][j][k] = 0.f;

    gemm_main(g_xi + (size_t)t0 * KP,
              g_wb + ((size_t)mat * DM_ + n0) * KP, sm, tid, acc);

    #pragma unroll
    for (int mi = 0; mi < 2; ++mi) {
        #pragma unroll
        for (int ni = 0; ni < 8; ++ni) {
            const int cl = wn * 64 + ni * 8 + (lane & 3) * 2;
            const int ng = n0 + cl;
            const int h = ng >> 6, d = ng & 63;
            const float b0v = bias[h * DH_ + d];
            const float b1v = bias[h * DH_ + d + 1];
            #pragma unroll
            for (int r8 = 0; r8 < 2; ++r8) {
                const int t = t0 + wm * 32 + mi * 16 + (lane >> 2) + r8 * 8;
                const int bb = t >> 10, ss = t & (S_ - 1);
                const float v0 = acc[mi][ni][2 * r8] + b0v;
                const float v1 = acc[mi][ni][2 * r8 + 1] + b1v;
                if (mat == 0) {
                    uint32_t u[3];
                    packA2(v0, v1, u);
                    uint32_t* dp = (uint32_t*)(g_Qi +
                        ((size_t)(bb * H_ + h) * S_ + ss) * KH + d * 3);
                    dp[0] = u[0]; dp[1] = u[1]; dp[2] = u[2];
                } else if (mat == 1) {
                    uint32_t u[3];
                    packB2(v0, v1, u);
                    uint32_t* dp = (uint32_t*)(g_Ki +
                        ((size_t)(bb * H_ + h) * S_ + ss) * KH + d * 3);
                    dp[0] = u[0]; dp[1] = u[1]; dp[2] = u[2];
                } else {
                    *(float2*)(g_V + ((size_t)(bb * H_ + h) * S_ + ss) * DH_ + d)
                        = make_float2(v0, v1);
                }
            }
        }
    }
}

// ====================================================================
// K4: output dense. grid (32, 6), block 256, smem SMEM_G.
// ====================================================================
__global__ void __launch_bounds__(256, 2)
dense_mma(const float* __restrict__ bd)
{
    extern __shared__ char sm[];
    const int tid = threadIdx.x, lane = tid & 31, wid = tid >> 5;
    const int wm = wid & 3, wn = wid >> 2;

    const int t0 = blockIdx.x * 128;
    const int n0 = blockIdx.y * 128;

    float acc[2][8][4];
    #pragma unroll
    for (int i = 0; i < 2; ++i)
        #pragma unroll
        for (int j = 0; j < 8; ++j)
            #pragma unroll
            for (int k = 0; k < 4; ++k) acc[i][j][k] = 0.f;

    gemm_main(g_ai + (size_t)t0 * KP, g_wdb + (size_t)n0 * KP, sm, tid, acc);

    #pragma unroll
    for (int mi = 0; mi < 2; ++mi) {
        #pragma unroll
        for (int ni = 0; ni < 8; ++ni) {
            const int cl = wn * 64 + ni * 8 + (lane & 3) * 2;
            const float b0v = bd[n0 + cl];
            const float b1v = bd[n0 + cl + 1];
            #pragma unroll
            for (int r8 = 0; r8 < 2; ++r8) {
                const int t = t0 + wm * 32 + mi * 16 + (lane >> 2) + r8 * 8;
                float2 o = make_float2(acc[mi][ni][2 * r8] + b0v,
                                       acc[mi][ni][2 * r8 + 1] + b1v);
                *(float2*)(g_y + (size_t)t * DM_ + n0 + cl) = o;
            }
        }
    }
}

// ====================================================================
// K3: in-place normalization of the weights region of d_out.
// grid B*S*H (49152), block 256 — fully parallel, bandwidth-bound.
// ====================================================================
__global__ void __launch_bounds__(256)
normw_kernel(float* __restrict__ out)
{
    const int row = blockIdx.x;          // (b*S + s)*H + h
    const int h  = row % H_;
    const int bs = row / H_;
    const int s  = bs & (S_ - 1);
    const int b  = bs >> 10;
    const float m    = g_m[(b * H_ + h) * S_ + s];
    const float invl = 1.0f / g_l[(b * H_ + h) * S_ + s];

    size_t base = (size_t)row * S_ + threadIdx.x * 4;
    float4 p = *(float4*)(out + base);
    p.x = __expf(p.x - m) * invl;
    p.y = __expf(p.y - m) * invl;
    p.z = __expf(p.z - m) * invl;
    p.w = __expf(p.w - m) * invl;
    *(float4*)(out + base) = p;
}

// ====================================================================
// K2: attention on mma.sync with split-3 triples.
// grid (8, 12, 4), block 256 (8 warps x 16 q-rows), smem 204800 B.
// ====================================================================
#define ASTR   400
#define QS_OFF 0u
#define KS_OFF 51200u
#define VS_OFF 102400u
#define PS_OFF 153600u
#define SMEM_ATT 204800

__device__ __forceinline__ void attn_issue(uint32_t smu, int tid, int kt,
                                           const __nv_bfloat16* Ki_h,
                                           const __nv_bfloat16* Vt_h)
{
    if (kt >= 16) return;
    const uint32_t kb = smu + KS_OFF + (uint32_t)(kt & 1) * 25600u;
    const uint32_t vb = smu + VS_OFF + (uint32_t)(kt & 1) * 25600u;
    #pragma unroll
    for (int r = 0; r < 6; ++r) {
        int idx = tid + r * 256;
        int row = idx / 24, col = idx - row * 24;
        cpasync16(kb + row * ASTR + col * 16,
                  Ki_h + ((size_t)(kt * 64 + row)) * KH + col * 8);
        cpasync16(vb + row * ASTR + col * 16,
                  Vt_h + (size_t)row * (3 * S_) + kt * 192 + col * 8);
    }
}

__global__ void __launch_bounds__(256)
attn_mma(float* __restrict__ out)
{
    extern __shared__ char sm[];
    const int tid = threadIdx.x, lane = tid & 31, wid = tid >> 5;
    const int b = blockIdx.z, h = blockIdx.y;
    const int q0 = blockIdx.x * 128;
    const int bh = b * H_ + h;
    const __nv_bfloat16* Qi_h = g_Qi + (size_t)bh * S_ * KH;
    const __nv_bfloat16* Ki_h = g_Ki + (size_t)bh * S_ * KH;
    const __nv_bfloat16* Vt_h = g_Vt + (size_t)bh * DH_ * (3 * S_);
    const uint32_t smu = smem_u32(sm);

    #pragma unroll
    for (int r = 0; r < 12; ++r) {
        int idx = tid + r * 256;
        int row = idx / 24, col = idx - row * 24;
        cpasync16(smu + QS_OFF + row * ASTR + col * 16,
                  Qi_h + (size_t)(q0 + row) * KH + col * 8);
    }
    attn_issue(smu, tid, 0, Ki_h, Vt_h);
    CP_COMMIT();
    attn_issue(smu, tid, 1, Ki_h, Vt_h);
    CP_COMMIT();

    const uint32_t faoff = (uint32_t)((wid * 16 + (lane & 15)) * ASTR +
                                      ((lane >> 4) & 1) * 16);
    const uint32_t fboff = (uint32_t)(((lane & 7) + ((lane & 16) >> 1)) * ASTR +
                                      (lane & 8) * 2);

    float ctx[8][4];
    #pragma unroll
    for (int i = 0; i < 8; ++i)
        #pragma unroll
        for (int j = 0; j < 4; ++j) ctx[i][j] = 0.f;
    float m0 = -1e30f, m1 = -1e30f, l0 = 0.f, l1 = 0.f;

    const int r0 = lane >> 2;
    const int srow0 = q0 + wid * 16 + r0;       // rows srow0 and srow0+8
    float* orow0 = out + ((size_t)(b * S_ + srow0) * H_ + h) * S_;
    float* orow1 = out + ((size_t)(b * S_ + srow0 + 8) * H_ + h) * S_;

    for (int kt = 0; kt < 16; ++kt) {
        CP_WAIT1();
        __syncthreads();

        const uint32_t kb = smu + KS_OFF + (uint32_t)(kt & 1) * 25600u;
        const uint32_t vb = smu + VS_OFF + (uint32_t)(kt & 1) * 25600u;

        // ---- QK^T over k''=192 ----
        float p[8][4];
        #pragma unroll
        for (int i = 0; i < 8; ++i)
            #pragma unroll
            for (int j = 0; j < 4; ++j) p[i][j] = 0.f;
        #pragma unroll
        for (int k16 = 0; k16 < 12; ++k16) {
            uint32_t a[4];
            ldsm4(a, smu + QS_OFF + faoff + k16 * 32);
            #pragma unroll
            for (int np = 0; np < 4; ++np) {
                uint32_t bv[4];
                ldsm4(bv, kb + fboff + np * 16 * ASTR + k16 * 32);
                mma_bf16(p[np * 2 + 0], a, bv[0], bv[1]);
                mma_bf16(p[np * 2 + 1], a, bv[2], bv[3]);
            }
        }

        // ---- scale + write raw scores ----
        #pragma unroll
        for (int ni = 0; ni < 8; ++ni) {
            #pragma unroll
            for (int j = 0; j < 4; ++j) p[ni][j] *= SQK;
            const int c = kt * 64 + ni * 8 + (lane & 3) * 2;
            *(float2*)(orow0 + c) = make_float2(p[ni][0], p[ni][1]);
            *(float2*)(orow1 + c) = make_float2(p[ni][2], p[ni][3]);
        }

        // ---- online softmax; P-triples into Ps (warp-private rows) ----
        float mx0 = -1e30f, mx1 = -1e30f;
        #pragma unroll
        for (int ni = 0; ni < 8; ++ni) {
            mx0 = fmaxf(mx0, fmaxf(p[ni][0], p[ni][1]));
            mx1 = fmaxf(mx1, fmaxf(p[ni][2], p[ni][3]));
        }
        mx0 = fmaxf(mx0, __shfl_xor_sync(0xffffffffu, mx0, 1));
        mx0 = fmaxf(mx0, __shfl_xor_sync(0xffffffffu, mx0, 2));
        mx1 = fmaxf(mx1, __shfl_xor_sync(0xffffffffu, mx1, 1));
        mx1 = fmaxf(mx1, __shfl_xor_sync(0xffffffffu, mx1, 2));
        const float mn0 = fmaxf(m0, mx0), mn1 = fmaxf(m1, mx1);
        const float f0 = __expf(m0 - mn0), f1 = __expf(m1 - mn1);
        m0 = mn0; m1 = mn1;

        float s0 = 0.f, s1 = 0.f;
        const uint32_t psrow0 = smu + PS_OFF + (wid * 16 + r0) * ASTR;
        const uint32_t psrow1 = psrow0 + 8 * ASTR;
        #pragma unroll
        for (int ni = 0; ni < 8; ++ni) {
            const float e0 = __expf(p[ni][0] - mn0);
            const float e1 = __expf(p[ni][1] - mn0);
            const float e2 = __expf(p[ni][2] - mn1);
            const float e3 = __expf(p[ni][3] - mn1);
            s0 += e0 + e1; s1 += e2 + e3;
            const int cb = (ni * 8 + (lane & 3) * 2) * 6;   // byte offset 6*c
            uint32_t u[3];
            packA2(e0, e1, u);
            *(uint32_t*)(sm + (psrow0 - smu) + cb + 0) = u[0];
            *(uint32_t*)(sm + (psrow0 - smu) + cb + 4) = u[1];
            *(uint32_t*)(sm + (psrow0 - smu) + cb + 8) = u[2];
            packA2(e2, e3, u);
            *(uint32_t*)(sm + (psrow1 - smu) + cb + 0) = u[0];
            *(uint32_t*)(sm + (psrow1 - smu) + cb + 4) = u[1];
            *(uint32_t*)(sm + (psrow1 - smu) + cb + 8) = u[2];
        }
        s0 += __shfl_xor_sync(0xffffffffu, s0, 1);
        s0 += __shfl_xor_sync(0xffffffffu, s0, 2);
        s1 += __shfl_xor_sync(0xffffffffu, s1, 1);
        s1 += __shfl_xor_sync(0xffffffffu, s1, 2);
        l0 = l0 * f0 + s0;
        l1 = l1 * f1 + s1;
        #pragma unroll
        for (int ni = 0; ni < 8; ++ni) {
            ctx[ni][0] *= f0; ctx[ni][1] *= f0;
            ctx[ni][2] *= f1; ctx[ni][3] *= f1;
        }
        __syncwarp();   // Ps rows are warp-private; warp-level fence suffices

        // ---- PV over n''=192 ----
        #pragma unroll
        for (int k16 = 0; k16 < 12; ++k16) {
            uint32_t a[4];
            ldsm4(a, smu + PS_OFF + faoff + k16 * 32);
            #pragma unroll
            for (int np = 0; np < 4; ++np) {
                uint32_t bv[4];
                ldsm4(bv, vb + fboff + np * 16 * ASTR + k16 * 32);
                mma_bf16(ctx[np * 2 + 0], a, bv[0], bv[1]);
                mma_bf16(ctx[np * 2 + 1], a, bv[2], bv[3]);
            }
        }
        __syncthreads();   // all warps done with Ks/Vs this stage

        attn_issue(smu, tid, kt + 2, Ki_h, Vt_h);
        CP_COMMIT();
    }

    // ---- epilogue: ctx/l -> A-triples into g_ai; store m,l ----
    const float inv0 = 1.f / l0, inv1 = 1.f / l1;
    const int t0row = b * S_ + srow0;
    #pragma unroll
    for (int ni = 0; ni < 8; ++ni) {
        const int d = ni * 8 + (lane & 3) * 2;
        uint32_t u[3];
        packA2(ctx[ni][0] * inv0, ctx[ni][1] * inv0, u);
        uint32_t* dp = (uint32_t*)(g_ai + (size_t)t0row * KP + (h * 64 + d) * 3);
        dp[0] = u[0]; dp[1] = u[1]; dp[2] = u[2];
        packA2(ctx[ni][2] * inv1, ctx[ni][3] * inv1, u);
        dp = (uint32_t*)(g_ai + (size_t)(t0row + 8) * KP + (h * 64 + d) * 3);
        dp[0] = u[0]; dp[1] = u[1]; dp[2] = u[2];
    }
    if ((lane & 3) == 0) {
        g_m[(size_t)bh * S_ + srow0] = m0;
        g_l[(size_t)bh * S_ + srow0] = l0;
        g_m[(size_t)bh * S_ + srow0 + 8] = m1;
        g_l[(size_t)bh * S_ + srow0 + 8] = l1;
    }
}

// ====================================================================
// K5: LayerNorm. grid T, block 256.
// ====================================================================
__global__ void __launch_bounds__(256)
ln_kernel(const float* __restrict__ gamma, const float* __restrict__ beta,
          float* __restrict__ out)
{
    __shared__ float row[DM_];
    __shared__ float red[8];

    const int t = blockIdx.x;
    const int tid = threadIdx.x;

    float s = 0.f;
    #pragma unroll
    for (int j = 0; j < 3; j++) {
        float v = g_y[(size_t)t * DM_ + tid + j * 256];
        row[tid + j * 256] = v;
        s += v;
    }
    #pragma unroll
    for (int o = 16; o > 0; o >>= 1) s += __shfl_xor_sync(0xffffffffu, s, o);
    if ((tid & 31) == 0) red[tid >> 5] = s;
    __syncthreads();
    float tot = red[0];
    #pragma unroll
    for (int i = 1; i < 8; i++) tot += red[i];
    const float mu = tot * (1.0f / DM_);
    __syncthreads();

    float vs = 0.f;
    #pragma unroll
    for (int j = 0; j < 3; j++) {
        float d = row[tid + j * 256] - mu;
        vs += d * d;
    }
    #pragma unroll
    for (int o = 16; o > 0; o >>= 1) vs += __shfl_xor_sync(0xffffffffu, vs, o);
    if ((tid & 31) == 0) red[tid >> 5] = vs;
    __syncthreads();
    float tv = red[0];
    #pragma unroll
    for (int i = 1; i < 8; i++) tv += red[i];
    const float scale = rsqrtf(tv * (1.0f / DM_) + 1e-12f);

    #pragma unroll
    for (int j = 0; j < 3; j++) {
        const int idx = tid + j * 256;
        out[WOFF + (size_t)t * DM_ + idx] =
            (row[idx] - mu) * scale * gamma[idx] + beta[idx];
    }
}

// ====================================================================
// launch
// ====================================================================
extern "C" void kernel_launch(void* const* d_in, const int* in_sizes, int n_in,
                              void* d_out, int out_size)
{
    (void)in_sizes; (void)n_in; (void)out_size;
    const float* x     = (const float*)d_in[0];
    const float* Wq    = (const float*)d_in[1];
    const float* bq    = (const float*)d_in[2];
    const float* Wk    = (const float*)d_in[3];
    const float* bk    = (const float*)d_in[4];
    const float* Wv    = (const float*)d_in[5];
    const float* bv    = (const float*)d_in[6];
    const float* Wd    = (const float*)d_in[7];
    const float* bd    = (const float*)d_in[8];
    const float* gamma = (const float*)d_in[9];
    const float* beta  = (const float*)d_in[10];
    float* out = (float*)d_out;

    cudaFuncSetAttribute(qkv_mma,
                         cudaFuncAttributeMaxDynamicSharedMemorySize, SMEM_G);
    cudaFuncSetAttribute(dense_mma,
                         cudaFuncAttributeMaxDynamicSharedMemorySize, SMEM_G);
    cudaFuncSetAttribute(attn_mma,
                         cudaFuncAttributeMaxDynamicSharedMemorySize, SMEM_ATT);

    conv_x<<<T_ * E_ / 8 / 256, 256>>>(x);
    conv_w<<<dim3(E_ / 64, H_, 3), 256>>>(Wq, Wk, Wv);

    // z = 0,1,2: Q/K/V GEMMs; z = 3: folded conv_wd blocks
    qkv_mma<<<dim3(T_ / 128, DM_ / 128, 4), 256, SMEM_G>>>(bq, bk, bv, Wd);

    vtrans<<<dim3(S_ / 64, B_ * H_), 256>>>();

    attn_mma<<<dim3(S_ / 128, H_, B_), 256, SMEM_ATT>>>(out);

    normw_kernel<<<B_ * S_ * H_, 256>>>(out);

    dense_mma<<<dim3(T_ / 128, DM_ / 128), 256, SMEM_G>>>(bd);

    ln_kernel<<<T_, 256>>>(gamma, beta, out);
}

// round 15
// speedup vs baseline: 1.1164x; 1.0073x over previous
#include <cuda_runtime.h>
#include <cuda_bf16.h>
#include <cstdint>
#include <cstddef>

// ---------------- problem constants ----------------
#define B_   4
#define S_   1024
#define H_   12
#define DH_  64
#define E_   768
#define DM_  768
#define T_   (B_ * S_)            // 4096 tokens
#define KP   2304                 // triple-expanded K for the big GEMMs
#define KH   192                  // triple-expanded head dim (3*64)
#define SQK  0.125f               // 1/sqrt(64)
#define WOFF ((size_t)B_ * S_ * H_ * S_)   // start of y in d_out

// ---------------- scratch (device globals; no allocation) ----------------
__device__ float g_y [T_ * DM_];
__device__ float g_m [B_ * H_ * S_];
__device__ float g_l [B_ * H_ * S_];
__device__ float g_V [B_ * H_ * S_ * DH_];          // V fp32 [bh][s][64]
// triple-expanded bf16 operands
__device__ __nv_bfloat16 g_xi [T_ * KP];            // x tokens (A order)
__device__ __nv_bfloat16 g_ai [T_ * KP];            // ctx tokens (A order)
__device__ __nv_bfloat16 g_wb [3 * DM_ * KP];       // qkv weights (B order)
__device__ __nv_bfloat16 g_wdb[DM_ * KP];           // dense weights (B order)
// attention operands
__device__ __nv_bfloat16 g_Qi [B_ * H_ * S_ * KH];  // Q A-triples [bh][s][192]
__device__ __nv_bfloat16 g_Ki [B_ * H_ * S_ * KH];  // K B-triples [bh][s][192]
__device__ __nv_bfloat16 g_Vt [B_ * H_ * DH_ * 3 * S_]; // V B-triples [bh][d][3s]

// ---------------- mma.sync / ldmatrix / cp.async helpers ----------------
typedef unsigned long long ull;

__device__ __forceinline__ uint32_t smem_u32(const void* p) {
    uint32_t a;
    asm("{ .reg .u64 t; cvta.to.shared.u64 t, %1; cvt.u32.u64 %0, t; }"
        : "=r"(a) : "l"(p));
    return a;
}
__device__ __forceinline__ void ldsm4(uint32_t r[4], uint32_t addr) {
    asm volatile("ldmatrix.sync.aligned.m8n8.x4.shared.b16 {%0,%1,%2,%3}, [%4];"
                 : "=r"(r[0]), "=r"(r[1]), "=r"(r[2]), "=r"(r[3]) : "r"(addr));
}
__device__ __forceinline__ void mma_bf16(float d[4], const uint32_t a[4],
                                         uint32_t b0, uint32_t b1) {
    asm volatile(
        "mma.sync.aligned.m16n8k16.row.col.f32.bf16.bf16.f32 "
        "{%0,%1,%2,%3}, {%4,%5,%6,%7}, {%8,%9}, {%0,%1,%2,%3};"
        : "+f"(d[0]), "+f"(d[1]), "+f"(d[2]), "+f"(d[3])
        : "r"(a[0]), "r"(a[1]), "r"(a[2]), "r"(a[3]), "r"(b0), "r"(b1));
}
__device__ __forceinline__ void cpasync16(uint32_t dst, const void* src) {
    asm volatile("cp.async.cg.shared.global [%0], [%1], 16;\n"
                 :: "r"(dst), "l"(src));
}
#define CP_COMMIT() asm volatile("cp.async.commit_group;\n" ::)
#define CP_WAIT1()  asm volatile("cp.async.wait_group 1;\n" ::)

// triple expansion: A side (h,h,l); B side (h,l,h).
__device__ __forceinline__ void tripleA(float v, __nv_bfloat16* o) {
    __nv_bfloat16 h = __float2bfloat16_rn(v);
    __nv_bfloat16 l = __float2bfloat16_rn(v - __bfloat162float(h));
    o[0] = h; o[1] = h; o[2] = l;
}
__device__ __forceinline__ void tripleB(float v, __nv_bfloat16* o) {
    __nv_bfloat16 h = __float2bfloat16_rn(v);
    __nv_bfloat16 l = __float2bfloat16_rn(v - __bfloat162float(h));
    o[0] = h; o[1] = l; o[2] = h;
}
// packed pair-of-triples (two consecutive values -> 3 uint32)
__device__ __forceinline__ void packA2(float v0, float v1, uint32_t u[3]) {
    __nv_bfloat16 h0 = __float2bfloat16_rn(v0);
    __nv_bfloat16 l0 = __float2bfloat16_rn(v0 - __bfloat162float(h0));
    __nv_bfloat16 h1 = __float2bfloat16_rn(v1);
    __nv_bfloat16 l1 = __float2bfloat16_rn(v1 - __bfloat162float(h1));
    uint32_t H0 = __bfloat16_as_ushort(h0), L0 = __bfloat16_as_ushort(l0);
    uint32_t H1 = __bfloat16_as_ushort(h1), L1 = __bfloat16_as_ushort(l1);
    u[0] = H0 | (H0 << 16); u[1] = L0 | (H1 << 16); u[2] = H1 | (L1 << 16);
}
__device__ __forceinline__ void packB2(float v0, float v1, uint32_t u[3]) {
    __nv_bfloat16 h0 = __float2bfloat16_rn(v0);
    __nv_bfloat16 l0 = __float2bfloat16_rn(v0 - __bfloat162float(h0));
    __nv_bfloat16 h1 = __float2bfloat16_rn(v1);
    __nv_bfloat16 l1 = __float2bfloat16_rn(v1 - __bfloat162float(h1));
    uint32_t H0 = __bfloat16_as_ushort(h0), L0 = __bfloat16_as_ushort(l0);
    uint32_t H1 = __bfloat16_as_ushort(h1), L1 = __bfloat16_as_ushort(l1);
    u[0] = H0 | (L0 << 16); u[1] = H0 | (H1 << 16); u[2] = L1 | (H1 << 16);
}

// ---------------- GEMM geometry (KC=64, 3-stage) ----------------
#define KC      64
#define NCHUNK  (KP / KC)           // 36
#define ROWB    144                 // 128B data + 16B pad per smem row
#define STAGE_A (128 * ROWB)        // 18432 B
#define STAGE_B (2 * STAGE_A)       // 36864 B per stage (A + B)
#define SMEM_G  (3 * STAGE_B)       // 110592 B

__device__ __forceinline__ void g_issue(uint32_t smu, int tid, int c,
                                        const __nv_bfloat16* Arows,
                                        const __nv_bfloat16* Brows)
{
    const uint32_t base = smu + (uint32_t)(c % 3) * STAGE_B;
    const int k0 = c * KC;
    #pragma unroll
    for (int r = 0; r < 4; ++r) {
        int idx = tid + r * 256;                 // 0..1023
        int row = idx >> 3, c16 = idx & 7;       // 128 rows x 8 16B-cols
        cpasync16(base + row * ROWB + c16 * 16,
                  Arows + (size_t)row * KP + k0 + c16 * 8);
        cpasync16(base + STAGE_A + row * ROWB + c16 * 16,
                  Brows + (size_t)row * KP + k0 + c16 * 8);
    }
}

__device__ __forceinline__ void gemm_main(const __nv_bfloat16* Arows,
                                          const __nv_bfloat16* Brows,
                                          char* sm, int tid,
                                          float acc[2][8][4])
{
    const int lane = tid & 31, wid = tid >> 5;
    const int wm = wid & 3, wn = wid >> 2;
    const uint32_t smu = smem_u32(sm);

    g_issue(smu, tid, 0, Arows, Brows); CP_COMMIT();
    g_issue(smu, tid, 1, Arows, Brows); CP_COMMIT();

    const uint32_t faoff = (uint32_t)((wm * 32 + (lane & 15)) * ROWB +
                                      ((lane >> 4) & 1) * 16);
    const uint32_t fboff = (uint32_t)(STAGE_A +
                           (wn * 64 + (lane & 7) + ((lane & 16) >> 1)) * ROWB +
                           (lane & 8) * 2);

    for (int c = 0; c < NCHUNK; ++c) {
        CP_WAIT1();
        __syncthreads();
        if (c + 2 < NCHUNK) g_issue(smu, tid, c + 2, Arows, Brows);
        CP_COMMIT();

        const uint32_t sb = smu + (uint32_t)(c % 3) * STAGE_B;
        const uint32_t fa = sb + faoff;
        const uint32_t fb = sb + fboff;
        #pragma unroll
        for (int k16 = 0; k16 < 4; ++k16) {
            uint32_t a0[4], a1[4];
            ldsm4(a0, fa + k16 * 32);
            ldsm4(a1, fa + 16 * ROWB + k16 * 32);
            #pragma unroll
            for (int np = 0; np < 4; ++np) {
                uint32_t bh[4];
                ldsm4(bh, fb + np * 16 * ROWB + k16 * 32);
                mma_bf16(acc[0][np * 2 + 0], a0, bh[0], bh[1]);
                mma_bf16(acc[0][np * 2 + 1], a0, bh[2], bh[3]);
                mma_bf16(acc[1][np * 2 + 0], a1, bh[0], bh[1]);
                mma_bf16(acc[1][np * 2 + 1], a1, bh[2], bh[3]);
            }
        }
    }
}

// ====================================================================
// conversion kernels
// ====================================================================
__global__ void __launch_bounds__(256)
conv_x(const float* __restrict__ x)
{
    const size_t g = (size_t)blockIdx.x * 256 + threadIdx.x;
    const float* src = x + g * 8;
    uint4 buf4[3];
    __nv_bfloat16* buf = (__nv_bfloat16*)buf4;
    float4 v0 = *(const float4*)(src);
    float4 v1 = *(const float4*)(src + 4);
    tripleA(v0.x, buf + 0);  tripleA(v0.y, buf + 3);
    tripleA(v0.z, buf + 6);  tripleA(v0.w, buf + 9);
    tripleA(v1.x, buf + 12); tripleA(v1.y, buf + 15);
    tripleA(v1.z, buf + 18); tripleA(v1.w, buf + 21);
    uint4* dp = (uint4*)(g_xi + g * 24);
    dp[0] = buf4[0]; dp[1] = buf4[1]; dp[2] = buf4[2];
}

__global__ void __launch_bounds__(256)
conv_w(const float* __restrict__ Wq, const float* __restrict__ Wk,
       const float* __restrict__ Wv)
{
    __shared__ float tile[64][65];
    const int e0  = blockIdx.x * 64;
    const int h   = blockIdx.y;
    const int mat = blockIdx.z;
    const float* W = (mat == 0) ? Wq : (mat == 1) ? Wk : Wv;
    const int tid = threadIdx.x;

    #pragma unroll
    for (int r = 0; r < 16; ++r) {
        int idx = tid + r * 256;
        int el = idx >> 6, d = idx & 63;
        tile[el][d] = W[((size_t)h * E_ + e0 + el) * DH_ + d];
    }
    __syncthreads();

    const int d = tid >> 2, eg = tid & 3;
    uint4 buf4[6];
    __nv_bfloat16* buf = (__nv_bfloat16*)buf4;
    #pragma unroll
    for (int i = 0; i < 16; ++i)
        tripleB(tile[eg * 16 + i][d], buf + 3 * i);
    uint4* dp = (uint4*)(g_wb + ((size_t)mat * DM_ + h * 64 + d) * KP +
                         (size_t)(e0 + eg * 16) * 3);
    #pragma unroll
    for (int j = 0; j < 6; ++j) dp[j] = buf4[j];
}

// V transpose + triple expansion: g_V [bh][s][64] -> g_Vt [bh][d][3s]
__global__ void __launch_bounds__(256)
vtrans()
{
    __shared__ float tile[64][65];
    const int s0 = blockIdx.x * 64;
    const int bh = blockIdx.y;
    const int tid = threadIdx.x;

    #pragma unroll
    for (int r = 0; r < 16; ++r) {
        int idx = tid + r * 256;
        int s = idx >> 6, d = idx & 63;
        tile[s][d] = g_V[((size_t)bh * S_ + s0 + s) * DH_ + d];
    }
    __syncthreads();

    const int d = tid >> 2, sg = tid & 3;
    uint4 buf4[6];
    __nv_bfloat16* buf = (__nv_bfloat16*)buf4;
    #pragma unroll
    for (int i = 0; i < 16; ++i)
        tripleB(tile[sg * 16 + i][d], buf + 3 * i);
    uint4* dp = (uint4*)(g_Vt + ((size_t)bh * DH_ + d) * (3 * S_) +
                         (size_t)(s0 + sg * 16) * 3);
    #pragma unroll
    for (int j = 0; j < 6; ++j) dp[j] = buf4[j];
}

// ====================================================================
// K1: QKV projection (z = 0,1,2) + folded conv_wd blocks (z = 3).
// Epilogue: Q -> g_Qi (A-triples), K -> g_Ki (B-triples), V -> g_V fp32.
// ====================================================================
__global__ void __launch_bounds__(256, 2)
qkv_mma(const float* __restrict__ bq, const float* __restrict__ bk,
        const float* __restrict__ bv, const float* __restrict__ Wd)
{
    extern __shared__ char sm[];
    const int tid = threadIdx.x, lane = tid & 31, wid = tid >> 5;
    const int wm = wid & 3, wn = wid >> 2;

    const int mat = blockIdx.z;
    if (mat == 3) {
        // folded conv_wd: Wd[k][n] -> g_wdb[n][3k..] (B order)
        const int idx = blockIdx.y * 32 + blockIdx.x;
        if (idx >= 144) return;
        __shared__ float tile[64][65];
        const int k0 = (idx / 12) * 64;
        const int n0 = (idx % 12) * 64;
        #pragma unroll
        for (int r = 0; r < 16; ++r) {
            int ii = tid + r * 256;
            int kl = ii >> 6, nl = ii & 63;
            tile[kl][nl] = Wd[(size_t)(k0 + kl) * DM_ + n0 + nl];
        }
        __syncthreads();
        const int nl = tid >> 2, kg = tid & 3;
        uint4 buf4[6];
        __nv_bfloat16* buf = (__nv_bfloat16*)buf4;
        #pragma unroll
        for (int i = 0; i < 16; ++i)
            tripleB(tile[kg * 16 + i][nl], buf + 3 * i);
        uint4* dp = (uint4*)(g_wdb + (size_t)(n0 + nl) * KP +
                             (size_t)(k0 + kg * 16) * 3);
        #pragma unroll
        for (int j = 0; j < 6; ++j) dp[j] = buf4[j];
        return;
    }

    const float* bias = (mat == 0) ? bq : (mat == 1) ? bk : bv;

    const int t0 = blockIdx.x * 128;
    const int n0 = blockIdx.y * 128;

    float acc[2][8][4];
    #pragma unroll
    for (int i = 0; i < 2; ++i)
        #pragma unroll
        for (int j = 0; j < 8; ++j)
            #pragma unroll
            for (int k = 0; k < 4; ++k) acc[i][j][k] = 0.f;

    gemm_main(g_xi + (size_t)t0 * KP,
              g_wb + ((size_t)mat * DM_ + n0) * KP, sm, tid, acc);

    #pragma unroll
    for (int mi = 0; mi < 2; ++mi) {
        #pragma unroll
        for (int ni = 0; ni < 8; ++ni) {
            const int cl = wn * 64 + ni * 8 + (lane & 3) * 2;
            const int ng = n0 + cl;
            const int h = ng >> 6, d = ng & 63;
            const float b0v = bias[h * DH_ + d];
            const float b1v = bias[h * DH_ + d + 1];
            #pragma unroll
            for (int r8 = 0; r8 < 2; ++r8) {
                const int t = t0 + wm * 32 + mi * 16 + (lane >> 2) + r8 * 8;
                const int bb = t >> 10, ss = t & (S_ - 1);
                const float v0 = acc[mi][ni][2 * r8] + b0v;
                const float v1 = acc[mi][ni][2 * r8 + 1] + b1v;
                if (mat == 0) {
                    uint32_t u[3];
                    packA2(v0, v1, u);
                    uint32_t* dp = (uint32_t*)(g_Qi +
                        ((size_t)(bb * H_ + h) * S_ + ss) * KH + d * 3);
                    dp[0] = u[0]; dp[1] = u[1]; dp[2] = u[2];
                } else if (mat == 1) {
                    uint32_t u[3];
                    packB2(v0, v1, u);
                    uint32_t* dp = (uint32_t*)(g_Ki +
                        ((size_t)(bb * H_ + h) * S_ + ss) * KH + d * 3);
                    dp[0] = u[0]; dp[1] = u[1]; dp[2] = u[2];
                } else {
                    *(float2*)(g_V + ((size_t)(bb * H_ + h) * S_ + ss) * DH_ + d)
                        = make_float2(v0, v1);
                }
            }
        }
    }
}

// ====================================================================
// K4: output dense. grid (32, 6), block 256, smem SMEM_G.
// ====================================================================
__global__ void __launch_bounds__(256, 2)
dense_mma(const float* __restrict__ bd)
{
    extern __shared__ char sm[];
    const int tid = threadIdx.x, lane = tid & 31, wid = tid >> 5;
    const int wm = wid & 3, wn = wid >> 2;

    const int t0 = blockIdx.x * 128;
    const int n0 = blockIdx.y * 128;

    float acc[2][8][4];
    #pragma unroll
    for (int i = 0; i < 2; ++i)
        #pragma unroll
        for (int j = 0; j < 8; ++j)
            #pragma unroll
            for (int k = 0; k < 4; ++k) acc[i][j][k] = 0.f;

    gemm_main(g_ai + (size_t)t0 * KP, g_wdb + (size_t)n0 * KP, sm, tid, acc);

    #pragma unroll
    for (int mi = 0; mi < 2; ++mi) {
        #pragma unroll
        for (int ni = 0; ni < 8; ++ni) {
            const int cl = wn * 64 + ni * 8 + (lane & 3) * 2;
            const float b0v = bd[n0 + cl];
            const float b1v = bd[n0 + cl + 1];
            #pragma unroll
            for (int r8 = 0; r8 < 2; ++r8) {
                const int t = t0 + wm * 32 + mi * 16 + (lane >> 2) + r8 * 8;
                float2 o = make_float2(acc[mi][ni][2 * r8] + b0v,
                                       acc[mi][ni][2 * r8 + 1] + b1v);
                *(float2*)(g_y + (size_t)t * DM_ + n0 + cl) = o;
            }
        }
    }
}

// ====================================================================
// K3: in-place normalization of the weights region of d_out.
// grid B*S*H (49152), block 256 — fully parallel, bandwidth-bound.
// ====================================================================
__global__ void __launch_bounds__(256)
normw_kernel(float* __restrict__ out)
{
    const int row = blockIdx.x;          // (b*S + s)*H + h
    const int h  = row % H_;
    const int bs = row / H_;
    const int s  = bs & (S_ - 1);
    const int b  = bs >> 10;
    const float m    = g_m[(b * H_ + h) * S_ + s];
    const float invl = 1.0f / g_l[(b * H_ + h) * S_ + s];

    size_t base = (size_t)row * S_ + threadIdx.x * 4;
    float4 p = *(float4*)(out + base);
    p.x = __expf(p.x - m) * invl;
    p.y = __expf(p.y - m) * invl;
    p.z = __expf(p.z - m) * invl;
    p.w = __expf(p.w - m) * invl;
    *(float4*)(out + base) = p;
}

// ====================================================================
// K2: attention on mma.sync with split-3 triples.
// grid (8, 12, 4), block 256 (8 warps x 16 q-rows), smem 204800 B.
// ====================================================================
#define ASTR   400
#define QS_OFF 0u
#define KS_OFF 51200u
#define VS_OFF 102400u
#define PS_OFF 153600u
#define SMEM_ATT 204800

__device__ __forceinline__ void attn_issue(uint32_t smu, int tid, int kt,
                                           const __nv_bfloat16* Ki_h,
                                           const __nv_bfloat16* Vt_h)
{
    if (kt >= 16) return;
    const uint32_t kb = smu + KS_OFF + (uint32_t)(kt & 1) * 25600u;
    const uint32_t vb = smu + VS_OFF + (uint32_t)(kt & 1) * 25600u;
    #pragma unroll
    for (int r = 0; r < 6; ++r) {
        int idx = tid + r * 256;
        int row = idx / 24, col = idx - row * 24;
        cpasync16(kb + row * ASTR + col * 16,
                  Ki_h + ((size_t)(kt * 64 + row)) * KH + col * 8);
        cpasync16(vb + row * ASTR + col * 16,
                  Vt_h + (size_t)row * (3 * S_) + kt * 192 + col * 8);
    }
}

__global__ void __launch_bounds__(256)
attn_mma(float* __restrict__ out)
{
    extern __shared__ char sm[];
    const int tid = threadIdx.x, lane = tid & 31, wid = tid >> 5;
    const int b = blockIdx.z, h = blockIdx.y;
    const int q0 = blockIdx.x * 128;
    const int bh = b * H_ + h;
    const __nv_bfloat16* Qi_h = g_Qi + (size_t)bh * S_ * KH;
    const __nv_bfloat16* Ki_h = g_Ki + (size_t)bh * S_ * KH;
    const __nv_bfloat16* Vt_h = g_Vt + (size_t)bh * DH_ * (3 * S_);
    const uint32_t smu = smem_u32(sm);

    #pragma unroll
    for (int r = 0; r < 12; ++r) {
        int idx = tid + r * 256;
        int row = idx / 24, col = idx - row * 24;
        cpasync16(smu + QS_OFF + row * ASTR + col * 16,
                  Qi_h + (size_t)(q0 + row) * KH + col * 8);
    }
    attn_issue(smu, tid, 0, Ki_h, Vt_h);
    CP_COMMIT();
    attn_issue(smu, tid, 1, Ki_h, Vt_h);
    CP_COMMIT();

    const uint32_t faoff = (uint32_t)((wid * 16 + (lane & 15)) * ASTR +
                                      ((lane >> 4) & 1) * 16);
    const uint32_t fboff = (uint32_t)(((lane & 7) + ((lane & 16) >> 1)) * ASTR +
                                      (lane & 8) * 2);

    float ctx[8][4];
    #pragma unroll
    for (int i = 0; i < 8; ++i)
        #pragma unroll
        for (int j = 0; j < 4; ++j) ctx[i][j] = 0.f;
    float m0 = -1e30f, m1 = -1e30f, l0 = 0.f, l1 = 0.f;

    const int r0 = lane >> 2;
    const int srow0 = q0 + wid * 16 + r0;       // rows srow0 and srow0+8
    float* orow0 = out + ((size_t)(b * S_ + srow0) * H_ + h) * S_;
    float* orow1 = out + ((size_t)(b * S_ + srow0 + 8) * H_ + h) * S_;

    for (int kt = 0; kt < 16; ++kt) {
        CP_WAIT1();
        __syncthreads();

        const uint32_t kb = smu + KS_OFF + (uint32_t)(kt & 1) * 25600u;
        const uint32_t vb = smu + VS_OFF + (uint32_t)(kt & 1) * 25600u;

        // ---- QK^T over k''=192 ----
        float p[8][4];
        #pragma unroll
        for (int i = 0; i < 8; ++i)
            #pragma unroll
            for (int j = 0; j < 4; ++j) p[i][j] = 0.f;
        #pragma unroll
        for (int k16 = 0; k16 < 12; ++k16) {
            uint32_t a[4];
            ldsm4(a, smu + QS_OFF + faoff + k16 * 32);
            #pragma unroll
            for (int np = 0; np < 4; ++np) {
                uint32_t bv[4];
                ldsm4(bv, kb + fboff + np * 16 * ASTR + k16 * 32);
                mma_bf16(p[np * 2 + 0], a, bv[0], bv[1]);
                mma_bf16(p[np * 2 + 1], a, bv[2], bv[3]);
            }
        }

        // ---- scale + write raw scores ----
        #pragma unroll
        for (int ni = 0; ni < 8; ++ni) {
            #pragma unroll
            for (int j = 0; j < 4; ++j) p[ni][j] *= SQK;
            const int c = kt * 64 + ni * 8 + (lane & 3) * 2;
            *(float2*)(orow0 + c) = make_float2(p[ni][0], p[ni][1]);
            *(float2*)(orow1 + c) = make_float2(p[ni][2], p[ni][3]);
        }

        // ---- online softmax; P-triples into Ps (warp-private rows) ----
        float mx0 = -1e30f, mx1 = -1e30f;
        #pragma unroll
        for (int ni = 0; ni < 8; ++ni) {
            mx0 = fmaxf(mx0, fmaxf(p[ni][0], p[ni][1]));
            mx1 = fmaxf(mx1, fmaxf(p[ni][2], p[ni][3]));
        }
        mx0 = fmaxf(mx0, __shfl_xor_sync(0xffffffffu, mx0, 1));
        mx0 = fmaxf(mx0, __shfl_xor_sync(0xffffffffu, mx0, 2));
        mx1 = fmaxf(mx1, __shfl_xor_sync(0xffffffffu, mx1, 1));
        mx1 = fmaxf(mx1, __shfl_xor_sync(0xffffffffu, mx1, 2));
        const float mn0 = fmaxf(m0, mx0), mn1 = fmaxf(m1, mx1);
        const float f0 = __expf(m0 - mn0), f1 = __expf(m1 - mn1);
        m0 = mn0; m1 = mn1;

        float s0 = 0.f, s1 = 0.f;
        const uint32_t psrow0 = smu + PS_OFF + (wid * 16 + r0) * ASTR;
        const uint32_t psrow1 = psrow0 + 8 * ASTR;
        #pragma unroll
        for (int ni = 0; ni < 8; ++ni) {
            const float e0 = __expf(p[ni][0] - mn0);
            const float e1 = __expf(p[ni][1] - mn0);
            const float e2 = __expf(p[ni][2] - mn1);
            const float e3 = __expf(p[ni][3] - mn1);
            s0 += e0 + e1; s1 += e2 + e3;
            const int cb = (ni * 8 + (lane & 3) * 2) * 6;   // byte offset 6*c
            uint32_t u[3];
            packA2(e0, e1, u);
            *(uint32_t*)(sm + (psrow0 - smu) + cb + 0) = u[0];
            *(uint32_t*)(sm + (psrow0 - smu) + cb + 4) = u[1];
            *(uint32_t*)(sm + (psrow0 - smu) + cb + 8) = u[2];
            packA2(e2, e3, u);
            *(uint32_t*)(sm + (psrow1 - smu) + cb + 0) = u[0];
            *(uint32_t*)(sm + (psrow1 - smu) + cb + 4) = u[1];
            *(uint32_t*)(sm + (psrow1 - smu) + cb + 8) = u[2];
        }
        s0 += __shfl_xor_sync(0xffffffffu, s0, 1);
        s0 += __shfl_xor_sync(0xffffffffu, s0, 2);
        s1 += __shfl_xor_sync(0xffffffffu, s1, 1);
        s1 += __shfl_xor_sync(0xffffffffu, s1, 2);
        l0 = l0 * f0 + s0;
        l1 = l1 * f1 + s1;
        #pragma unroll
        for (int ni = 0; ni < 8; ++ni) {
            ctx[ni][0] *= f0; ctx[ni][1] *= f0;
            ctx[ni][2] *= f1; ctx[ni][3] *= f1;
        }
        __syncwarp();   // Ps rows are warp-private; warp-level fence suffices

        // ---- PV over n''=192 ----
        #pragma unroll
        for (int k16 = 0; k16 < 12; ++k16) {
            uint32_t a[4];
            ldsm4(a, smu + PS_OFF + faoff + k16 * 32);
            #pragma unroll
            for (int np = 0; np < 4; ++np) {
                uint32_t bv[4];
                ldsm4(bv, vb + fboff + np * 16 * ASTR + k16 * 32);
                mma_bf16(ctx[np * 2 + 0], a, bv[0], bv[1]);
                mma_bf16(ctx[np * 2 + 1], a, bv[2], bv[3]);
            }
        }
        __syncthreads();   // all warps done with Ks/Vs this stage

        attn_issue(smu, tid, kt + 2, Ki_h, Vt_h);
        CP_COMMIT();
    }

    // ---- epilogue: ctx/l -> A-triples into g_ai; store m,l ----
    const float inv0 = 1.f / l0, inv1 = 1.f / l1;
    const int t0row = b * S_ + srow0;
    #pragma unroll
    for (int ni = 0; ni < 8; ++ni) {
        const int d = ni * 8 + (lane & 3) * 2;
        uint32_t u[3];
        packA2(ctx[ni][0] * inv0, ctx[ni][1] * inv0, u);
        uint32_t* dp = (uint32_t*)(g_ai + (size_t)t0row * KP + (h * 64 + d) * 3);
        dp[0] = u[0]; dp[1] = u[1]; dp[2] = u[2];
        packA2(ctx[ni][2] * inv1, ctx[ni][3] * inv1, u);
        dp = (uint32_t*)(g_ai + (size_t)(t0row + 8) * KP + (h * 64 + d) * 3);
        dp[0] = u[0]; dp[1] = u[1]; dp[2] = u[2];
    }
    if ((lane & 3) == 0) {
        g_m[(size_t)bh * S_ + srow0] = m0;
        g_l[(size_t)bh * S_ + srow0] = l0;
        g_m[(size_t)bh * S_ + srow0 + 8] = m1;
        g_l[(size_t)bh * S_ + srow0 + 8] = l1;
    }
}

// ====================================================================
// K5: LayerNorm. grid T, block 256.
// ====================================================================
__global__ void __launch_bounds__(256)
ln_kernel(const float* __restrict__ gamma, const float* __restrict__ beta,
          float* __restrict__ out)
{
    __shared__ float row[DM_];
    __shared__ float red[8];

    const int t = blockIdx.x;
    const int tid = threadIdx.x;

    float s = 0.f;
    #pragma unroll
    for (int j = 0; j < 3; j++) {
        float v = g_y[(size_t)t * DM_ + tid + j * 256];
        row[tid + j * 256] = v;
        s += v;
    }
    #pragma unroll
    for (int o = 16; o > 0; o >>= 1) s += __shfl_xor_sync(0xffffffffu, s, o);
    if ((tid & 31) == 0) red[tid >> 5] = s;
    __syncthreads();
    float tot = red[0];
    #pragma unroll
    for (int i = 1; i < 8; i++) tot += red[i];
    const float mu = tot * (1.0f / DM_);
    __syncthreads();

    float vs = 0.f;
    #pragma unroll
    for (int j = 0; j < 3; j++) {
        float d = row[tid + j * 256] - mu;
        vs += d * d;
    }
    #pragma unroll
    for (int o = 16; o > 0; o >>= 1) vs += __shfl_xor_sync(0xffffffffu, vs, o);
    if ((tid & 31) == 0) red[tid >> 5] = vs;
    __syncthreads();
    float tv = red[0];
    #pragma unroll
    for (int i = 1; i < 8; i++) tv += red[i];
    const float scale = rsqrtf(tv * (1.0f / DM_) + 1e-12f);

    #pragma unroll
    for (int j = 0; j < 3; j++) {
        const int idx = tid + j * 256;
        out[WOFF + (size_t)t * DM_ + idx] =
            (row[idx] - mu) * scale * gamma[idx] + beta[idx];
    }
}

// ====================================================================
// launch
// ====================================================================
extern "C" void kernel_launch(void* const* d_in, const int* in_sizes, int n_in,
                              void* d_out, int out_size)
{
    (void)in_sizes; (void)n_in; (void)out_size;
    const float* x     = (const float*)d_in[0];
    const float* Wq    = (const float*)d_in[1];
    const float* bq    = (const float*)d_in[2];
    const float* Wk    = (const float*)d_in[3];
    const float* bk    = (const float*)d_in[4];
    const float* Wv    = (const float*)d_in[5];
    const float* bv    = (const float*)d_in[6];
    const float* Wd    = (const float*)d_in[7];
    const float* bd    = (const float*)d_in[8];
    const float* gamma = (const float*)d_in[9];
    const float* beta  = (const float*)d_in[10];
    float* out = (float*)d_out;

    cudaFuncSetAttribute(qkv_mma,
                         cudaFuncAttributeMaxDynamicSharedMemorySize, SMEM_G);
    cudaFuncSetAttribute(dense_mma,
                         cudaFuncAttributeMaxDynamicSharedMemorySize, SMEM_G);
    cudaFuncSetAttribute(attn_mma,
                         cudaFuncAttributeMaxDynamicSharedMemorySize, SMEM_ATT);

    conv_x<<<T_ * E_ / 8 / 256, 256>>>(x);
    conv_w<<<dim3(E_ / 64, H_, 3), 256>>>(Wq, Wk, Wv);

    // z = 0,1,2: Q/K/V GEMMs; z = 3: folded conv_wd blocks
    qkv_mma<<<dim3(T_ / 128, DM_ / 128, 4), 256, SMEM_G>>>(bq, bk, bv, Wd);

    vtrans<<<dim3(S_ / 64, B_ * H_), 256>>>();

    attn_mma<<<dim3(S_ / 128, H_, B_), 256, SMEM_ATT>>>(out);

    normw_kernel<<<B_ * S_ * H_, 256>>>(out);

    // dense overlaps normw via programmatic dependent launch (independent
    // buffers: dense reads g_ai/g_wdb, writes g_y; normw touches d_out scores).
    {
        cudaLaunchConfig_t cfg = {};
        cfg.gridDim = dim3(T_ / 128, DM_ / 128, 1);
        cfg.blockDim = dim3(256, 1, 1);
        cfg.dynamicSmemBytes = SMEM_G;
        cfg.stream = 0;
        cudaLaunchAttribute attr[1];
        attr[0].id = cudaLaunchAttributeProgrammaticStreamSerialization;
        attr[0].val.programmaticStreamSerializationAllowed = 1;
        cfg.attrs = attr;
        cfg.numAttrs = 1;
        cudaError_t e = cudaLaunchKernelEx(&cfg, dense_mma, bd);
        if (e != cudaSuccess) {
            cudaGetLastError();   // clear; fall back to a plain launch
            dense_mma<<<dim3(T_ / 128, DM_ / 128), 256, SMEM_G>>>(bd);
        }
    }

    ln_kernel<<<T_, 256>>>(gamma, beta, out);
}

// round 16
// speedup vs baseline: 1.4959x; 1.3399x over previous
#include <cuda_runtime.h>
#include <cuda_fp16.h>
#include <cuda_bf16.h>
#include <cstdint>
#include <cstddef>

// ---------------- problem constants ----------------
#define B_   4
#define S_   1024
#define H_   12
#define DH_  64
#define E_   768
#define DM_  768
#define T_   (B_ * S_)            // 4096 tokens
#define KP   1536                 // pair-expanded K for the big GEMMs (2x)
#define KH   128                  // pair-expanded head dim (2*64)
#define SQK  0.125f               // 1/sqrt(64)
#define WOFF ((size_t)B_ * S_ * H_ * S_)   // start of y in d_out

// ---------------- scratch (device globals; no allocation) ----------------
__device__ float g_y [T_ * DM_];
__device__ float g_m [B_ * H_ * S_];
__device__ float g_l [B_ * H_ * S_];
__device__ float g_V [B_ * H_ * S_ * DH_];          // V fp32 [bh][s][64]
// pair-expanded fp16 operands (diagonal split-2: both sides (hi,lo))
__device__ __half g_xi [T_ * KP];                   // x tokens
__device__ __half g_ai [T_ * KP];                   // ctx tokens
__device__ __half g_wb [3 * DM_ * KP];              // qkv weights
__device__ __half g_wdb[DM_ * KP];                  // dense weights
// attention operands
__device__ __half g_Qi [B_ * H_ * S_ * KH];         // Q pairs [bh][s][128]
__device__ __half g_Ki [B_ * H_ * S_ * KH];         // K pairs [bh][s][128]
__device__ __half g_Vt [B_ * H_ * DH_ * 2 * S_];    // V pairs [bh][d][2s]

// ---------------- mma.sync / ldmatrix / cp.async helpers ----------------
typedef unsigned long long ull;

__device__ __forceinline__ uint32_t smem_u32(const void* p) {
    uint32_t a;
    asm("{ .reg .u64 t; cvta.to.shared.u64 t, %1; cvt.u32.u64 %0, t; }"
        : "=r"(a) : "l"(p));
    return a;
}
__device__ __forceinline__ void ldsm4(uint32_t r[4], uint32_t addr) {
    asm volatile("ldmatrix.sync.aligned.m8n8.x4.shared.b16 {%0,%1,%2,%3}, [%4];"
                 : "=r"(r[0]), "=r"(r[1]), "=r"(r[2]), "=r"(r[3]) : "r"(addr));
}
__device__ __forceinline__ void mma_f16(float d[4], const uint32_t a[4],
                                        uint32_t b0, uint32_t b1) {
    asm volatile(
        "mma.sync.aligned.m16n8k16.row.col.f32.f16.f16.f32 "
        "{%0,%1,%2,%3}, {%4,%5,%6,%7}, {%8,%9}, {%0,%1,%2,%3};"
        : "+f"(d[0]), "+f"(d[1]), "+f"(d[2]), "+f"(d[3])
        : "r"(a[0]), "r"(a[1]), "r"(a[2]), "r"(a[3]), "r"(b0), "r"(b1));
}
__device__ __forceinline__ void cpasync16(uint32_t dst, const void* src) {
    asm volatile("cp.async.cg.shared.global [%0], [%1], 16;\n"
                 :: "r"(dst), "l"(src));
}
#define CP_COMMIT() asm volatile("cp.async.commit_group;\n" ::)
#define CP_WAIT1()  asm volatile("cp.async.wait_group 1;\n" ::)

// fp16 split-2: v = h + l with |l| <= 2^-11 |v|; diagonal pairing (h,l) on
// BOTH operands -> dot over expanded K gives ah*bh + al*bl (cross terms
// ~2^-12 relative are dropped; empirically ~4e-4 aggregate rel err).
__device__ __forceinline__ void pairHL(float v, __half* o) {
    __half h = __float2half_rn(v);
    __half l = __float2half_rn(v - __half2float(h));
    o[0] = h; o[1] = l;
}
// two consecutive values -> 2 packed uint32 (4 halves)
__device__ __forceinline__ void pack2(float v0, float v1, uint32_t u[2]) {
    __half h0 = __float2half_rn(v0);
    __half l0 = __float2half_rn(v0 - __half2float(h0));
    __half h1 = __float2half_rn(v1);
    __half l1 = __float2half_rn(v1 - __half2float(h1));
    u[0] = (uint32_t)__half_as_ushort(h0) | ((uint32_t)__half_as_ushort(l0) << 16);
    u[1] = (uint32_t)__half_as_ushort(h1) | ((uint32_t)__half_as_ushort(l1) << 16);
}

// ---------------- GEMM geometry (KC=64, 3-stage) ----------------
#define KC      64
#define NCHUNK  (KP / KC)           // 24
#define ROWB    144                 // 128B data + 16B pad per smem row
#define STAGE_A (128 * ROWB)        // 18432 B
#define STAGE_B (2 * STAGE_A)       // 36864 B per stage (A + B)
#define SMEM_G  (3 * STAGE_B)       // 110592 B

__device__ __forceinline__ void g_issue(uint32_t smu, int tid, int c,
                                        const __half* Arows,
                                        const __half* Brows)
{
    const uint32_t base = smu + (uint32_t)(c % 3) * STAGE_B;
    const int k0 = c * KC;
    #pragma unroll
    for (int r = 0; r < 4; ++r) {
        int idx = tid + r * 256;                 // 0..1023
        int row = idx >> 3, c16 = idx & 7;       // 128 rows x 8 16B-cols
        cpasync16(base + row * ROWB + c16 * 16,
                  Arows + (size_t)row * KP + k0 + c16 * 8);
        cpasync16(base + STAGE_A + row * ROWB + c16 * 16,
                  Brows + (size_t)row * KP + k0 + c16 * 8);
    }
}

__device__ __forceinline__ void gemm_main(const __half* Arows,
                                          const __half* Brows,
                                          char* sm, int tid,
                                          float acc[2][8][4])
{
    const int lane = tid & 31, wid = tid >> 5;
    const int wm = wid & 3, wn = wid >> 2;
    const uint32_t smu = smem_u32(sm);

    g_issue(smu, tid, 0, Arows, Brows); CP_COMMIT();
    g_issue(smu, tid, 1, Arows, Brows); CP_COMMIT();

    const uint32_t faoff = (uint32_t)((wm * 32 + (lane & 15)) * ROWB +
                                      ((lane >> 4) & 1) * 16);
    const uint32_t fboff = (uint32_t)(STAGE_A +
                           (wn * 64 + (lane & 7) + ((lane & 16) >> 1)) * ROWB +
                           (lane & 8) * 2);

    for (int c = 0; c < NCHUNK; ++c) {
        CP_WAIT1();
        __syncthreads();
        if (c + 2 < NCHUNK) g_issue(smu, tid, c + 2, Arows, Brows);
        CP_COMMIT();

        const uint32_t sb = smu + (uint32_t)(c % 3) * STAGE_B;
        const uint32_t fa = sb + faoff;
        const uint32_t fb = sb + fboff;
        #pragma unroll
        for (int k16 = 0; k16 < 4; ++k16) {
            uint32_t a0[4], a1[4];
            ldsm4(a0, fa + k16 * 32);
            ldsm4(a1, fa + 16 * ROWB + k16 * 32);
            #pragma unroll
            for (int np = 0; np < 4; ++np) {
                uint32_t bh[4];
                ldsm4(bh, fb + np * 16 * ROWB + k16 * 32);
                mma_f16(acc[0][np * 2 + 0], a0, bh[0], bh[1]);
                mma_f16(acc[0][np * 2 + 1], a0, bh[2], bh[3]);
                mma_f16(acc[1][np * 2 + 0], a1, bh[0], bh[1]);
                mma_f16(acc[1][np * 2 + 1], a1, bh[2], bh[3]);
            }
        }
    }
}

// ====================================================================
// conversion kernels
// ====================================================================
__global__ void __launch_bounds__(256)
conv_x(const float* __restrict__ x)
{
    const size_t g = (size_t)blockIdx.x * 256 + threadIdx.x;
    const float* src = x + g * 8;
    uint4 buf4[2];
    __half* buf = (__half*)buf4;
    float4 v0 = *(const float4*)(src);
    float4 v1 = *(const float4*)(src + 4);
    pairHL(v0.x, buf + 0);  pairHL(v0.y, buf + 2);
    pairHL(v0.z, buf + 4);  pairHL(v0.w, buf + 6);
    pairHL(v1.x, buf + 8);  pairHL(v1.y, buf + 10);
    pairHL(v1.z, buf + 12); pairHL(v1.w, buf + 14);
    uint4* dp = (uint4*)(g_xi + g * 16);
    dp[0] = buf4[0]; dp[1] = buf4[1];
}

__global__ void __launch_bounds__(256)
conv_w(const float* __restrict__ Wq, const float* __restrict__ Wk,
       const float* __restrict__ Wv)
{
    __shared__ float tile[64][65];
    const int e0  = blockIdx.x * 64;
    const int h   = blockIdx.y;
    const int mat = blockIdx.z;
    const float* W = (mat == 0) ? Wq : (mat == 1) ? Wk : Wv;
    const int tid = threadIdx.x;

    #pragma unroll
    for (int r = 0; r < 16; ++r) {
        int idx = tid + r * 256;
        int el = idx >> 6, d = idx & 63;
        tile[el][d] = W[((size_t)h * E_ + e0 + el) * DH_ + d];
    }
    __syncthreads();

    const int d = tid >> 2, eg = tid & 3;
    uint4 buf4[4];
    __half* buf = (__half*)buf4;
    #pragma unroll
    for (int i = 0; i < 16; ++i)
        pairHL(tile[eg * 16 + i][d], buf + 2 * i);
    uint4* dp = (uint4*)(g_wb + ((size_t)mat * DM_ + h * 64 + d) * KP +
                         (size_t)(e0 + eg * 16) * 2);
    #pragma unroll
    for (int j = 0; j < 4; ++j) dp[j] = buf4[j];
}

// V transpose + pair expansion: g_V [bh][s][64] -> g_Vt [bh][d][2s]
__global__ void __launch_bounds__(256)
vtrans()
{
    __shared__ float tile[64][65];
    const int s0 = blockIdx.x * 64;
    const int bh = blockIdx.y;
    const int tid = threadIdx.x;

    #pragma unroll
    for (int r = 0; r < 16; ++r) {
        int idx = tid + r * 256;
        int s = idx >> 6, d = idx & 63;
        tile[s][d] = g_V[((size_t)bh * S_ + s0 + s) * DH_ + d];
    }
    __syncthreads();

    const int d = tid >> 2, sg = tid & 3;
    uint4 buf4[4];
    __half* buf = (__half*)buf4;
    #pragma unroll
    for (int i = 0; i < 16; ++i)
        pairHL(tile[sg * 16 + i][d], buf + 2 * i);
    uint4* dp = (uint4*)(g_Vt + ((size_t)bh * DH_ + d) * (2 * S_) +
                         (size_t)(s0 + sg * 16) * 2);
    #pragma unroll
    for (int j = 0; j < 4; ++j) dp[j] = buf4[j];
}

// ====================================================================
// K1: QKV projection (z = 0,1,2) + folded conv_wd blocks (z = 3).
// Epilogue: Q -> g_Qi pairs, K -> g_Ki pairs, V -> g_V fp32.
// ====================================================================
__global__ void __launch_bounds__(256, 2)
qkv_mma(const float* __restrict__ bq, const float* __restrict__ bk,
        const float* __restrict__ bv, const float* __restrict__ Wd)
{
    extern __shared__ char sm[];
    const int tid = threadIdx.x, lane = tid & 31, wid = tid >> 5;
    const int wm = wid & 3, wn = wid >> 2;

    const int mat = blockIdx.z;
    if (mat == 3) {
        // folded conv_wd: Wd[k][n] -> g_wdb[n][2k..]
        const int idx = blockIdx.y * 32 + blockIdx.x;
        if (idx >= 144) return;
        __shared__ float tile[64][65];
        const int k0 = (idx / 12) * 64;
        const int n0 = (idx % 12) * 64;
        #pragma unroll
        for (int r = 0; r < 16; ++r) {
            int ii = tid + r * 256;
            int kl = ii >> 6, nl = ii & 63;
            tile[kl][nl] = Wd[(size_t)(k0 + kl) * DM_ + n0 + nl];
        }
        __syncthreads();
        const int nl = tid >> 2, kg = tid & 3;
        uint4 buf4[4];
        __half* buf = (__half*)buf4;
        #pragma unroll
        for (int i = 0; i < 16; ++i)
            pairHL(tile[kg * 16 + i][nl], buf + 2 * i);
        uint4* dp = (uint4*)(g_wdb + (size_t)(n0 + nl) * KP +
                             (size_t)(k0 + kg * 16) * 2);
        #pragma unroll
        for (int j = 0; j < 4; ++j) dp[j] = buf4[j];
        return;
    }

    const float* bias = (mat == 0) ? bq : (mat == 1) ? bk : bv;

    const int t0 = blockIdx.x * 128;
    const int n0 = blockIdx.y * 128;

    float acc[2][8][4];
    #pragma unroll
    for (int i = 0; i < 2; ++i)
        #pragma unroll
        for (int j = 0; j < 8; ++j)
            #pragma unroll
            for (int k = 0; k < 4; ++k) acc[i][j][k] = 0.f;

    gemm_main(g_xi + (size_t)t0 * KP,
              g_wb + ((size_t)mat * DM_ + n0) * KP, sm, tid, acc);

    #pragma unroll
    for (int mi = 0; mi < 2; ++mi) {
        #pragma unroll
        for (int ni = 0; ni < 8; ++ni) {
            const int cl = wn * 64 + ni * 8 + (lane & 3) * 2;
            const int ng = n0 + cl;
            const int h = ng >> 6, d = ng & 63;
            const float b0v = bias[h * DH_ + d];
            const float b1v = bias[h * DH_ + d + 1];
            #pragma unroll
            for (int r8 = 0; r8 < 2; ++r8) {
                const int t = t0 + wm * 32 + mi * 16 + (lane >> 2) + r8 * 8;
                const int bb = t >> 10, ss = t & (S_ - 1);
                const float v0 = acc[mi][ni][2 * r8] + b0v;
                const float v1 = acc[mi][ni][2 * r8 + 1] + b1v;
                if (mat == 0) {
                    uint32_t u[2];
                    pack2(v0, v1, u);
                    uint2* dp = (uint2*)(g_Qi +
                        ((size_t)(bb * H_ + h) * S_ + ss) * KH + d * 2);
                    *dp = make_uint2(u[0], u[1]);
                } else if (mat == 1) {
                    uint32_t u[2];
                    pack2(v0, v1, u);
                    uint2* dp = (uint2*)(g_Ki +
                        ((size_t)(bb * H_ + h) * S_ + ss) * KH + d * 2);
                    *dp = make_uint2(u[0], u[1]);
                } else {
                    *(float2*)(g_V + ((size_t)(bb * H_ + h) * S_ + ss) * DH_ + d)
                        = make_float2(v0, v1);
                }
            }
        }
    }
}

// ====================================================================
// K4: output dense. grid (32, 6), block 256, smem SMEM_G.
// ====================================================================
__global__ void __launch_bounds__(256, 2)
dense_mma(const float* __restrict__ bd)
{
    extern __shared__ char sm[];
    const int tid = threadIdx.x, lane = tid & 31, wid = tid >> 5;
    const int wm = wid & 3, wn = wid >> 2;

    const int t0 = blockIdx.x * 128;
    const int n0 = blockIdx.y * 128;

    float acc[2][8][4];
    #pragma unroll
    for (int i = 0; i < 2; ++i)
        #pragma unroll
        for (int j = 0; j < 8; ++j)
            #pragma unroll
            for (int k = 0; k < 4; ++k) acc[i][j][k] = 0.f;

    gemm_main(g_ai + (size_t)t0 * KP, g_wdb + (size_t)n0 * KP, sm, tid, acc);

    #pragma unroll
    for (int mi = 0; mi < 2; ++mi) {
        #pragma unroll
        for (int ni = 0; ni < 8; ++ni) {
            const int cl = wn * 64 + ni * 8 + (lane & 3) * 2;
            const float b0v = bd[n0 + cl];
            const float b1v = bd[n0 + cl + 1];
            #pragma unroll
            for (int r8 = 0; r8 < 2; ++r8) {
                const int t = t0 + wm * 32 + mi * 16 + (lane >> 2) + r8 * 8;
                float2 o = make_float2(acc[mi][ni][2 * r8] + b0v,
                                       acc[mi][ni][2 * r8 + 1] + b1v);
                *(float2*)(g_y + (size_t)t * DM_ + n0 + cl) = o;
            }
        }
    }
}

// ====================================================================
// K3: in-place normalization of the weights region of d_out.
// ====================================================================
__global__ void __launch_bounds__(256)
normw_kernel(float* __restrict__ out)
{
    const int row = blockIdx.x;          // (b*S + s)*H + h
    const int h  = row % H_;
    const int bs = row / H_;
    const int s  = bs & (S_ - 1);
    const int b  = bs >> 10;
    const float m    = g_m[(b * H_ + h) * S_ + s];
    const float invl = 1.0f / g_l[(b * H_ + h) * S_ + s];

    size_t base = (size_t)row * S_ + threadIdx.x * 4;
    float4 p = *(float4*)(out + base);
    p.x = __expf(p.x - m) * invl;
    p.y = __expf(p.y - m) * invl;
    p.z = __expf(p.z - m) * invl;
    p.w = __expf(p.w - m) * invl;
    *(float4*)(out + base) = p;
}

// ====================================================================
// K2: attention on mma.sync with fp16 split-2 pairs.
// grid (8, 12, 4), block 256 (8 warps x 16 q-rows), smem 139264 B.
// ====================================================================
#define ASTR   272
#define QTILE  (128 * ASTR)         // 34816
#define KTILE  (64 * ASTR)          // 17408
#define QS_OFF 0u
#define KS_OFF 34816u
#define VS_OFF 69632u
#define PS_OFF 104448u
#define SMEM_ATT 139264

__device__ __forceinline__ void attn_issue(uint32_t smu, int tid, int kt,
                                           const __half* Ki_h,
                                           const __half* Vt_h)
{
    if (kt >= 16) return;
    const uint32_t kb = smu + KS_OFF + (uint32_t)(kt & 1) * KTILE;
    const uint32_t vb = smu + VS_OFF + (uint32_t)(kt & 1) * KTILE;
    #pragma unroll
    for (int r = 0; r < 4; ++r) {
        int idx = tid + r * 256;                // 0..1023
        int row = idx >> 4, col = idx & 15;     // 64 rows x 16 16B-cols
        cpasync16(kb + row * ASTR + col * 16,
                  Ki_h + ((size_t)(kt * 64 + row)) * KH + col * 8);
        cpasync16(vb + row * ASTR + col * 16,
                  Vt_h + (size_t)row * (2 * S_) + kt * 128 + col * 8);
    }
}

__global__ void __launch_bounds__(256)
attn_mma(float* __restrict__ out)
{
    extern __shared__ char sm[];
    const int tid = threadIdx.x, lane = tid & 31, wid = tid >> 5;
    const int b = blockIdx.z, h = blockIdx.y;
    const int q0 = blockIdx.x * 128;
    const int bh = b * H_ + h;
    const __half* Qi_h = g_Qi + (size_t)bh * S_ * KH;
    const __half* Ki_h = g_Ki + (size_t)bh * S_ * KH;
    const __half* Vt_h = g_Vt + (size_t)bh * DH_ * (2 * S_);
    const uint32_t smu = smem_u32(sm);

    #pragma unroll
    for (int r = 0; r < 8; ++r) {
        int idx = tid + r * 256;                // 0..2047
        int row = idx >> 4, col = idx & 15;     // 128 rows x 16 16B-cols
        cpasync16(smu + QS_OFF + row * ASTR + col * 16,
                  Qi_h + (size_t)(q0 + row) * KH + col * 8);
    }
    attn_issue(smu, tid, 0, Ki_h, Vt_h);
    CP_COMMIT();
    attn_issue(smu, tid, 1, Ki_h, Vt_h);
    CP_COMMIT();

    const uint32_t faoff = (uint32_t)((wid * 16 + (lane & 15)) * ASTR +
                                      ((lane >> 4) & 1) * 16);
    const uint32_t fboff = (uint32_t)(((lane & 7) + ((lane & 16) >> 1)) * ASTR +
                                      (lane & 8) * 2);

    float ctx[8][4];
    #pragma unroll
    for (int i = 0; i < 8; ++i)
        #pragma unroll
        for (int j = 0; j < 4; ++j) ctx[i][j] = 0.f;
    float m0 = -1e30f, m1 = -1e30f, l0 = 0.f, l1 = 0.f;

    const int r0 = lane >> 2;
    const int srow0 = q0 + wid * 16 + r0;       // rows srow0 and srow0+8
    float* orow0 = out + ((size_t)(b * S_ + srow0) * H_ + h) * S_;
    float* orow1 = out + ((size_t)(b * S_ + srow0 + 8) * H_ + h) * S_;

    for (int kt = 0; kt < 16; ++kt) {
        CP_WAIT1();
        __syncthreads();

        const uint32_t kb = smu + KS_OFF + (uint32_t)(kt & 1) * KTILE;
        const uint32_t vb = smu + VS_OFF + (uint32_t)(kt & 1) * KTILE;

        // ---- QK^T over k'=128 ----
        float p[8][4];
        #pragma unroll
        for (int i = 0; i < 8; ++i)
            #pragma unroll
            for (int j = 0; j < 4; ++j) p[i][j] = 0.f;
        #pragma unroll
        for (int k16 = 0; k16 < 8; ++k16) {
            uint32_t a[4];
            ldsm4(a, smu + QS_OFF + faoff + k16 * 32);
            #pragma unroll
            for (int np = 0; np < 4; ++np) {
                uint32_t bv[4];
                ldsm4(bv, kb + fboff + np * 16 * ASTR + k16 * 32);
                mma_f16(p[np * 2 + 0], a, bv[0], bv[1]);
                mma_f16(p[np * 2 + 1], a, bv[2], bv[3]);
            }
        }

        // ---- scale + write raw scores ----
        #pragma unroll
        for (int ni = 0; ni < 8; ++ni) {
            #pragma unroll
            for (int j = 0; j < 4; ++j) p[ni][j] *= SQK;
            const int c = kt * 64 + ni * 8 + (lane & 3) * 2;
            *(float2*)(orow0 + c) = make_float2(p[ni][0], p[ni][1]);
            *(float2*)(orow1 + c) = make_float2(p[ni][2], p[ni][3]);
        }

        // ---- online softmax; P pairs into Ps (warp-private rows) ----
        float mx0 = -1e30f, mx1 = -1e30f;
        #pragma unroll
        for (int ni = 0; ni < 8; ++ni) {
            mx0 = fmaxf(mx0, fmaxf(p[ni][0], p[ni][1]));
            mx1 = fmaxf(mx1, fmaxf(p[ni][2], p[ni][3]));
        }
        mx0 = fmaxf(mx0, __shfl_xor_sync(0xffffffffu, mx0, 1));
        mx0 = fmaxf(mx0, __shfl_xor_sync(0xffffffffu, mx0, 2));
        mx1 = fmaxf(mx1, __shfl_xor_sync(0xffffffffu, mx1, 1));
        mx1 = fmaxf(mx1, __shfl_xor_sync(0xffffffffu, mx1, 2));
        const float mn0 = fmaxf(m0, mx0), mn1 = fmaxf(m1, mx1);
        const float f0 = __expf(m0 - mn0), f1 = __expf(m1 - mn1);
        m0 = mn0; m1 = mn1;

        float s0 = 0.f, s1 = 0.f;
        const uint32_t psrow0 = smu + PS_OFF + (wid * 16 + r0) * ASTR;
        const uint32_t psrow1 = psrow0 + 8 * ASTR;
        #pragma unroll
        for (int ni = 0; ni < 8; ++ni) {
            const float e0 = __expf(p[ni][0] - mn0);
            const float e1 = __expf(p[ni][1] - mn0);
            const float e2 = __expf(p[ni][2] - mn1);
            const float e3 = __expf(p[ni][3] - mn1);
            s0 += e0 + e1; s1 += e2 + e3;
            const int cb = (ni * 8 + (lane & 3) * 2) * 4;   // byte offset 4*c
            uint32_t u[2];
            pack2(e0, e1, u);
            *(uint32_t*)(sm + (psrow0 - smu) + cb + 0) = u[0];
            *(uint32_t*)(sm + (psrow0 - smu) + cb + 4) = u[1];
            pack2(e2, e3, u);
            *(uint32_t*)(sm + (psrow1 - smu) + cb + 0) = u[0];
            *(uint32_t*)(sm + (psrow1 - smu) + cb + 4) = u[1];
        }
        s0 += __shfl_xor_sync(0xffffffffu, s0, 1);
        s0 += __shfl_xor_sync(0xffffffffu, s0, 2);
        s1 += __shfl_xor_sync(0xffffffffu, s1, 1);
        s1 += __shfl_xor_sync(0xffffffffu, s1, 2);
        l0 = l0 * f0 + s0;
        l1 = l1 * f1 + s1;
        #pragma unroll
        for (int ni = 0; ni < 8; ++ni) {
            ctx[ni][0] *= f0; ctx[ni][1] *= f0;
            ctx[ni][2] *= f1; ctx[ni][3] *= f1;
        }
        __syncwarp();   // Ps rows are warp-private; warp-level fence suffices

        // ---- PV over n'=128 ----
        #pragma unroll
        for (int k16 = 0; k16 < 8; ++k16) {
            uint32_t a[4];
            ldsm4(a, smu + PS_OFF + faoff + k16 * 32);
            #pragma unroll
            for (int np = 0; np < 4; ++np) {
                uint32_t bv[4];
                ldsm4(bv, vb + fboff + np * 16 * ASTR + k16 * 32);
                mma_f16(ctx[np * 2 + 0], a, bv[0], bv[1]);
                mma_f16(ctx[np * 2 + 1], a, bv[2], bv[3]);
            }
        }
        __syncthreads();   // all warps done with Ks/Vs this stage

        attn_issue(smu, tid, kt + 2, Ki_h, Vt_h);
        CP_COMMIT();
    }

    // ---- epilogue: ctx/l -> pairs into g_ai; store m,l ----
    const float inv0 = 1.f / l0, inv1 = 1.f / l1;
    const int t0row = b * S_ + srow0;
    #pragma unroll
    for (int ni = 0; ni < 8; ++ni) {
        const int d = ni * 8 + (lane & 3) * 2;
        uint32_t u[2];
        pack2(ctx[ni][0] * inv0, ctx[ni][1] * inv0, u);
        uint2* dp = (uint2*)(g_ai + (size_t)t0row * KP + (h * 64 + d) * 2);
        *dp = make_uint2(u[0], u[1]);
        pack2(ctx[ni][2] * inv1, ctx[ni][3] * inv1, u);
        dp = (uint2*)(g_ai + (size_t)(t0row + 8) * KP + (h * 64 + d) * 2);
        *dp = make_uint2(u[0], u[1]);
    }
    if ((lane & 3) == 0) {
        g_m[(size_t)bh * S_ + srow0] = m0;
        g_l[(size_t)bh * S_ + srow0] = l0;
        g_m[(size_t)bh * S_ + srow0 + 8] = m1;
        g_l[(size_t)bh * S_ + srow0 + 8] = l1;
    }
}

// ====================================================================
// K5: LayerNorm. grid T, block 256.
// ====================================================================
__global__ void __launch_bounds__(256)
ln_kernel(const float* __restrict__ gamma, const float* __restrict__ beta,
          float* __restrict__ out)
{
    __shared__ float row[DM_];
    __shared__ float red[8];

    const int t = blockIdx.x;
    const int tid = threadIdx.x;

    float s = 0.f;
    #pragma unroll
    for (int j = 0; j < 3; j++) {
        float v = g_y[(size_t)t * DM_ + tid + j * 256];
        row[tid + j * 256] = v;
        s += v;
    }
    #pragma unroll
    for (int o = 16; o > 0; o >>= 1) s += __shfl_xor_sync(0xffffffffu, s, o);
    if ((tid & 31) == 0) red[tid >> 5] = s;
    __syncthreads();
    float tot = red[0];
    #pragma unroll
    for (int i = 1; i < 8; i++) tot += red[i];
    const float mu = tot * (1.0f / DM_);
    __syncthreads();

    float vs = 0.f;
    #pragma unroll
    for (int j = 0; j < 3; j++) {
        float d = row[tid + j * 256] - mu;
        vs += d * d;
    }
    #pragma unroll
    for (int o = 16; o > 0; o >>= 1) vs += __shfl_xor_sync(0xffffffffu, vs, o);
    if ((tid & 31) == 0) red[tid >> 5] = vs;
    __syncthreads();
    float tv = red[0];
    #pragma unroll
    for (int i = 1; i < 8; i++) tv += red[i];
    const float scale = rsqrtf(tv * (1.0f / DM_) + 1e-12f);

    #pragma unroll
    for (int j = 0; j < 3; j++) {
        const int idx = tid + j * 256;
        out[WOFF + (size_t)t * DM_ + idx] =
            (row[idx] - mu) * scale * gamma[idx] + beta[idx];
    }
}

// ====================================================================
// launch
// ====================================================================
extern "C" void kernel_launch(void* const* d_in, const int* in_sizes, int n_in,
                              void* d_out, int out_size)
{
    (void)in_sizes; (void)n_in; (void)out_size;
    const float* x     = (const float*)d_in[0];
    const float* Wq    = (const float*)d_in[1];
    const float* bq    = (const float*)d_in[2];
    const float* Wk    = (const float*)d_in[3];
    const float* bk    = (const float*)d_in[4];
    const float* Wv    = (const float*)d_in[5];
    const float* bv    = (const float*)d_in[6];
    const float* Wd    = (const float*)d_in[7];
    const float* bd    = (const float*)d_in[8];
    const float* gamma = (const float*)d_in[9];
    const float* beta  = (const float*)d_in[10];
    float* out = (float*)d_out;

    cudaFuncSetAttribute(qkv_mma,
                         cudaFuncAttributeMaxDynamicSharedMemorySize, SMEM_G);
    cudaFuncSetAttribute(dense_mma,
                         cudaFuncAttributeMaxDynamicSharedMemorySize, SMEM_G);
    cudaFuncSetAttribute(attn_mma,
                         cudaFuncAttributeMaxDynamicSharedMemorySize, SMEM_ATT);

    conv_x<<<T_ * E_ / 8 / 256, 256>>>(x);
    conv_w<<<dim3(E_ / 64, H_, 3), 256>>>(Wq, Wk, Wv);

    // z = 0,1,2: Q/K/V GEMMs; z = 3: folded conv_wd blocks
    qkv_mma<<<dim3(T_ / 128, DM_ / 128, 4), 256, SMEM_G>>>(bq, bk, bv, Wd);

    vtrans<<<dim3(S_ / 64, B_ * H_), 256>>>();

    attn_mma<<<dim3(S_ / 128, H_, B_), 256, SMEM_ATT>>>(out);

    normw_kernel<<<B_ * S_ * H_, 256>>>(out);

    // dense overlaps normw via programmatic dependent launch (independent
    // buffers: dense reads g_ai/g_wdb, writes g_y; normw touches d_out scores).
    {
        cudaLaunchConfig_t cfg = {};
        cfg.gridDim = dim3(T_ / 128, DM_ / 128, 1);
        cfg.blockDim = dim3(256, 1, 1);
        cfg.dynamicSmemBytes = SMEM_G;
        cfg.stream = 0;
        cudaLaunchAttribute attr[1];
        attr[0].id = cudaLaunchAttributeProgrammaticStreamSerialization;
        attr[0].val.programmaticStreamSerializationAllowed = 1;
        cfg.attrs = attr;
        cfg.numAttrs = 1;
        cudaError_t e = cudaLaunchKernelEx(&cfg, dense_mma, bd);
        if (e != cudaSuccess) {
            cudaGetLastError();   // clear; fall back to a plain launch
            dense_mma<<<dim3(T_ / 128, DM_ / 128), 256, SMEM_G>>>(bd);
        }
    }

    ln_kernel<<<T_, 256>>>(gamma, beta, out);
}

// round 17
// speedup vs baseline: 1.5976x; 1.0680x over previous
#include <cuda_runtime.h>
#include <cuda_fp16.h>
#include <cstdint>
#include <cstddef>

// ---------------- problem constants ----------------
#define B_   4
#define S_   1024
#define H_   12
#define DH_  64
#define E_   768
#define DM_  768
#define T_   (B_ * S_)            // 4096 tokens
#define KP   1536                 // pair-expanded K for the big GEMMs (2x)
#define KH   128                  // pair-expanded head dim (2*64)
#define SQK  0.125f               // 1/sqrt(64)
#define WOFF ((size_t)B_ * S_ * H_ * S_)   // start of y in d_out

// ---------------- scratch (device globals; no allocation) ----------------
__device__ float g_y [T_ * DM_];
__device__ float g_V [B_ * H_ * S_ * DH_];          // V fp32 [bh][s][64]
// pair-expanded fp16 operands (diagonal split-2: both sides (hi,lo))
__device__ __half g_xi [T_ * KP];                   // x tokens
__device__ __half g_ai [T_ * KP];                   // ctx tokens
__device__ __half g_wb [3 * DM_ * KP];              // qkv weights
__device__ __half g_wdb[DM_ * KP];                  // dense weights
// attention operands
__device__ __half g_Qi [B_ * H_ * S_ * KH];         // Q pairs [bh][s][128]
__device__ __half g_Ki [B_ * H_ * S_ * KH];         // K pairs [bh][s][128]
__device__ __half g_Vt [B_ * H_ * DH_ * 2 * S_];    // V pairs [bh][d][2s]

// ---------------- mma.sync / ldmatrix / cp.async helpers ----------------
typedef unsigned long long ull;

__device__ __forceinline__ uint32_t smem_u32(const void* p) {
    uint32_t a;
    asm("{ .reg .u64 t; cvta.to.shared.u64 t, %1; cvt.u32.u64 %0, t; }"
        : "=r"(a) : "l"(p));
    return a;
}
__device__ __forceinline__ void ldsm4(uint32_t r[4], uint32_t addr) {
    asm volatile("ldmatrix.sync.aligned.m8n8.x4.shared.b16 {%0,%1,%2,%3}, [%4];"
                 : "=r"(r[0]), "=r"(r[1]), "=r"(r[2]), "=r"(r[3]) : "r"(addr));
}
__device__ __forceinline__ void mma_f16(float d[4], const uint32_t a[4],
                                        uint32_t b0, uint32_t b1) {
    asm volatile(
        "mma.sync.aligned.m16n8k16.row.col.f32.f16.f16.f32 "
        "{%0,%1,%2,%3}, {%4,%5,%6,%7}, {%8,%9}, {%0,%1,%2,%3};"
        : "+f"(d[0]), "+f"(d[1]), "+f"(d[2]), "+f"(d[3])
        : "r"(a[0]), "r"(a[1]), "r"(a[2]), "r"(a[3]), "r"(b0), "r"(b1));
}
__device__ __forceinline__ void cpasync16(uint32_t dst, const void* src) {
    asm volatile("cp.async.cg.shared.global [%0], [%1], 16;\n"
                 :: "r"(dst), "l"(src));
}
#define CP_COMMIT() asm volatile("cp.async.commit_group;\n" ::)
#define CP_WAIT1()  asm volatile("cp.async.wait_group 1;\n" ::)

// fp16 split-2: v = h + l; diagonal pairing on both operands.
__device__ __forceinline__ void pairHL(float v, __half* o) {
    __half h = __float2half_rn(v);
    __half l = __float2half_rn(v - __half2float(h));
    o[0] = h; o[1] = l;
}
__device__ __forceinline__ void pack2(float v0, float v1, uint32_t u[2]) {
    __half h0 = __float2half_rn(v0);
    __half l0 = __float2half_rn(v0 - __half2float(h0));
    __half h1 = __float2half_rn(v1);
    __half l1 = __float2half_rn(v1 - __half2float(h1));
    u[0] = (uint32_t)__half_as_ushort(h0) | ((uint32_t)__half_as_ushort(l0) << 16);
    u[1] = (uint32_t)__half_as_ushort(h1) | ((uint32_t)__half_as_ushort(l1) << 16);
}

// ---------------- GEMM geometry (KC=64, 3-stage) ----------------
#define KC      64
#define NCHUNK  (KP / KC)           // 24
#define ROWB    144                 // 128B data + 16B pad per smem row
#define STAGE_A (128 * ROWB)        // 18432 B
#define STAGE_B (2 * STAGE_A)       // 36864 B per stage (A + B)
#define SMEM_G  (3 * STAGE_B)       // 110592 B

__device__ __forceinline__ void g_issue(uint32_t smu, int tid, int c,
                                        const __half* Arows,
                                        const __half* Brows)
{
    const uint32_t base = smu + (uint32_t)(c % 3) * STAGE_B;
    const int k0 = c * KC;
    #pragma unroll
    for (int r = 0; r < 4; ++r) {
        int idx = tid + r * 256;                 // 0..1023
        int row = idx >> 3, c16 = idx & 7;       // 128 rows x 8 16B-cols
        cpasync16(base + row * ROWB + c16 * 16,
                  Arows + (size_t)row * KP + k0 + c16 * 8);
        cpasync16(base + STAGE_A + row * ROWB + c16 * 16,
                  Brows + (size_t)row * KP + k0 + c16 * 8);
    }
}

__device__ __forceinline__ void gemm_main(const __half* Arows,
                                          const __half* Brows,
                                          char* sm, int tid,
                                          float acc[2][8][4])
{
    const int lane = tid & 31, wid = tid >> 5;
    const int wm = wid & 3, wn = wid >> 2;
    const uint32_t smu = smem_u32(sm);

    g_issue(smu, tid, 0, Arows, Brows); CP_COMMIT();
    g_issue(smu, tid, 1, Arows, Brows); CP_COMMIT();

    const uint32_t faoff = (uint32_t)((wm * 32 + (lane & 15)) * ROWB +
                                      ((lane >> 4) & 1) * 16);
    const uint32_t fboff = (uint32_t)(STAGE_A +
                           (wn * 64 + (lane & 7) + ((lane & 16) >> 1)) * ROWB +
                           (lane & 8) * 2);

    for (int c = 0; c < NCHUNK; ++c) {
        CP_WAIT1();
        __syncthreads();
        if (c + 2 < NCHUNK) g_issue(smu, tid, c + 2, Arows, Brows);
        CP_COMMIT();

        const uint32_t sb = smu + (uint32_t)(c % 3) * STAGE_B;
        const uint32_t fa = sb + faoff;
        const uint32_t fb = sb + fboff;
        #pragma unroll
        for (int k16 = 0; k16 < 4; ++k16) {
            uint32_t a0[4], a1[4];
            ldsm4(a0, fa + k16 * 32);
            ldsm4(a1, fa + 16 * ROWB + k16 * 32);
            #pragma unroll
            for (int np = 0; np < 4; ++np) {
                uint32_t bh[4];
                ldsm4(bh, fb + np * 16 * ROWB + k16 * 32);
                mma_f16(acc[0][np * 2 + 0], a0, bh[0], bh[1]);
                mma_f16(acc[0][np * 2 + 1], a0, bh[2], bh[3]);
                mma_f16(acc[1][np * 2 + 0], a1, bh[0], bh[1]);
                mma_f16(acc[1][np * 2 + 1], a1, bh[2], bh[3]);
            }
        }
    }
}

// ====================================================================
// conversion kernels
// ====================================================================
__global__ void __launch_bounds__(256)
conv_x(const float* __restrict__ x)
{
    const size_t g = (size_t)blockIdx.x * 256 + threadIdx.x;
    const float* src = x + g * 8;
    uint4 buf4[2];
    __half* buf = (__half*)buf4;
    float4 v0 = *(const float4*)(src);
    float4 v1 = *(const float4*)(src + 4);
    pairHL(v0.x, buf + 0);  pairHL(v0.y, buf + 2);
    pairHL(v0.z, buf + 4);  pairHL(v0.w, buf + 6);
    pairHL(v1.x, buf + 8);  pairHL(v1.y, buf + 10);
    pairHL(v1.z, buf + 12); pairHL(v1.w, buf + 14);
    uint4* dp = (uint4*)(g_xi + g * 16);
    dp[0] = buf4[0]; dp[1] = buf4[1];
}

__global__ void __launch_bounds__(256)
conv_w(const float* __restrict__ Wq, const float* __restrict__ Wk,
       const float* __restrict__ Wv)
{
    __shared__ float tile[64][65];
    const int e0  = blockIdx.x * 64;
    const int h   = blockIdx.y;
    const int mat = blockIdx.z;
    const float* W = (mat == 0) ? Wq : (mat == 1) ? Wk : Wv;
    const int tid = threadIdx.x;

    #pragma unroll
    for (int r = 0; r < 16; ++r) {
        int idx = tid + r * 256;
        int el = idx >> 6, d = idx & 63;
        tile[el][d] = W[((size_t)h * E_ + e0 + el) * DH_ + d];
    }
    __syncthreads();

    const int d = tid >> 2, eg = tid & 3;
    uint4 buf4[4];
    __half* buf = (__half*)buf4;
    #pragma unroll
    for (int i = 0; i < 16; ++i)
        pairHL(tile[eg * 16 + i][d], buf + 2 * i);
    uint4* dp = (uint4*)(g_wb + ((size_t)mat * DM_ + h * 64 + d) * KP +
                         (size_t)(e0 + eg * 16) * 2);
    #pragma unroll
    for (int j = 0; j < 4; ++j) dp[j] = buf4[j];
}

// V transpose + pair expansion: g_V [bh][s][64] -> g_Vt [bh][d][2s]
__global__ void __launch_bounds__(256)
vtrans()
{
    __shared__ float tile[64][65];
    const int s0 = blockIdx.x * 64;
    const int bh = blockIdx.y;
    const int tid = threadIdx.x;

    #pragma unroll
    for (int r = 0; r < 16; ++r) {
        int idx = tid + r * 256;
        int s = idx >> 6, d = idx & 63;
        tile[s][d] = g_V[((size_t)bh * S_ + s0 + s) * DH_ + d];
    }
    __syncthreads();

    const int d = tid >> 2, sg = tid & 3;
    uint4 buf4[4];
    __half* buf = (__half*)buf4;
    #pragma unroll
    for (int i = 0; i < 16; ++i)
        pairHL(tile[sg * 16 + i][d], buf + 2 * i);
    uint4* dp = (uint4*)(g_Vt + ((size_t)bh * DH_ + d) * (2 * S_) +
                         (size_t)(s0 + sg * 16) * 2);
    #pragma unroll
    for (int j = 0; j < 4; ++j) dp[j] = buf4[j];
}

// ====================================================================
// K1: QKV projection (z = 0,1,2) + folded conv_wd blocks (z = 3).
// ====================================================================
__global__ void __launch_bounds__(256, 2)
qkv_mma(const float* __restrict__ bq, const float* __restrict__ bk,
        const float* __restrict__ bv, const float* __restrict__ Wd)
{
    extern __shared__ char sm[];
    const int tid = threadIdx.x, lane = tid & 31, wid = tid >> 5;
    const int wm = wid & 3, wn = wid >> 2;

    const int mat = blockIdx.z;
    if (mat == 3) {
        const int idx = blockIdx.y * 32 + blockIdx.x;
        if (idx >= 144) return;
        __shared__ float tile[64][65];
        const int k0 = (idx / 12) * 64;
        const int n0 = (idx % 12) * 64;
        #pragma unroll
        for (int r = 0; r < 16; ++r) {
            int ii = tid + r * 256;
            int kl = ii >> 6, nl = ii & 63;
            tile[kl][nl] = Wd[(size_t)(k0 + kl) * DM_ + n0 + nl];
        }
        __syncthreads();
        const int nl = tid >> 2, kg = tid & 3;
        uint4 buf4[4];
        __half* buf = (__half*)buf4;
        #pragma unroll
        for (int i = 0; i < 16; ++i)
            pairHL(tile[kg * 16 + i][nl], buf + 2 * i);
        uint4* dp = (uint4*)(g_wdb + (size_t)(n0 + nl) * KP +
                             (size_t)(k0 + kg * 16) * 2);
        #pragma unroll
        for (int j = 0; j < 4; ++j) dp[j] = buf4[j];
        return;
    }

    const float* bias = (mat == 0) ? bq : (mat == 1) ? bk : bv;

    const int t0 = blockIdx.x * 128;
    const int n0 = blockIdx.y * 128;

    float acc[2][8][4];
    #pragma unroll
    for (int i = 0; i < 2; ++i)
        #pragma unroll
        for (int j = 0; j < 8; ++j)
            #pragma unroll
            for (int k = 0; k < 4; ++k) acc[i][j][k] = 0.f;

    gemm_main(g_xi + (size_t)t0 * KP,
              g_wb + ((size_t)mat * DM_ + n0) * KP, sm, tid, acc);

    #pragma unroll
    for (int mi = 0; mi < 2; ++mi) {
        #pragma unroll
        for (int ni = 0; ni < 8; ++ni) {
            const int cl = wn * 64 + ni * 8 + (lane & 3) * 2;
            const int ng = n0 + cl;
            const int h = ng >> 6, d = ng & 63;
            const float b0v = bias[h * DH_ + d];
            const float b1v = bias[h * DH_ + d + 1];
            #pragma unroll
            for (int r8 = 0; r8 < 2; ++r8) {
                const int t = t0 + wm * 32 + mi * 16 + (lane >> 2) + r8 * 8;
                const int bb = t >> 10, ss = t & (S_ - 1);
                const float v0 = acc[mi][ni][2 * r8] + b0v;
                const float v1 = acc[mi][ni][2 * r8 + 1] + b1v;
                if (mat == 0) {
                    uint32_t u[2];
                    pack2(v0, v1, u);
                    uint2* dp = (uint2*)(g_Qi +
                        ((size_t)(bb * H_ + h) * S_ + ss) * KH + d * 2);
                    *dp = make_uint2(u[0], u[1]);
                } else if (mat == 1) {
                    uint32_t u[2];
                    pack2(v0, v1, u);
                    uint2* dp = (uint2*)(g_Ki +
                        ((size_t)(bb * H_ + h) * S_ + ss) * KH + d * 2);
                    *dp = make_uint2(u[0], u[1]);
                } else {
                    *(float2*)(g_V + ((size_t)(bb * H_ + h) * S_ + ss) * DH_ + d)
                        = make_float2(v0, v1);
                }
            }
        }
    }
}

// ====================================================================
// K4: output dense. grid (32, 6), block 256, smem SMEM_G.
// ====================================================================
__global__ void __launch_bounds__(256, 2)
dense_mma(const float* __restrict__ bd)
{
    extern __shared__ char sm[];
    const int tid = threadIdx.x, lane = tid & 31, wid = tid >> 5;
    const int wm = wid & 3, wn = wid >> 2;

    const int t0 = blockIdx.x * 128;
    const int n0 = blockIdx.y * 128;

    float acc[2][8][4];
    #pragma unroll
    for (int i = 0; i < 2; ++i)
        #pragma unroll
        for (int j = 0; j < 8; ++j)
            #pragma unroll
            for (int k = 0; k < 4; ++k) acc[i][j][k] = 0.f;

    gemm_main(g_ai + (size_t)t0 * KP, g_wdb + (size_t)n0 * KP, sm, tid, acc);

    #pragma unroll
    for (int mi = 0; mi < 2; ++mi) {
        #pragma unroll
        for (int ni = 0; ni < 8; ++ni) {
            const int cl = wn * 64 + ni * 8 + (lane & 3) * 2;
            const float b0v = bd[n0 + cl];
            const float b1v = bd[n0 + cl + 1];
            #pragma unroll
            for (int r8 = 0; r8 < 2; ++r8) {
                const int t = t0 + wm * 32 + mi * 16 + (lane >> 2) + r8 * 8;
                float2 o = make_float2(acc[mi][ni][2 * r8] + b0v,
                                       acc[mi][ni][2 * r8 + 1] + b1v);
                *(float2*)(g_y + (size_t)t * DM_ + n0 + cl) = o;
            }
        }
    }
}

// ====================================================================
// K2: attention on mma.sync with fp16 split-2 pairs + fused normw sweep.
// grid (8, 12, 4), block 256 (8 warps x 16 q-rows), smem 139264 B.
// ====================================================================
#define ASTR   272
#define KTILE  (64 * ASTR)          // 17408
#define QS_OFF 0u
#define KS_OFF 34816u
#define VS_OFF 69632u
#define PS_OFF 104448u
#define SMEM_ATT 139264

__device__ __forceinline__ void attn_issue(uint32_t smu, int tid, int kt,
                                           const __half* Ki_h,
                                           const __half* Vt_h)
{
    if (kt >= 16) return;
    const uint32_t kb = smu + KS_OFF + (uint32_t)(kt & 1) * KTILE;
    const uint32_t vb = smu + VS_OFF + (uint32_t)(kt & 1) * KTILE;
    #pragma unroll
    for (int r = 0; r < 4; ++r) {
        int idx = tid + r * 256;                // 0..1023
        int row = idx >> 4, col = idx & 15;     // 64 rows x 16 16B-cols
        cpasync16(kb + row * ASTR + col * 16,
                  Ki_h + ((size_t)(kt * 64 + row)) * KH + col * 8);
        cpasync16(vb + row * ASTR + col * 16,
                  Vt_h + (size_t)row * (2 * S_) + kt * 128 + col * 8);
    }
}

__global__ void __launch_bounds__(256)
attn_mma(float* __restrict__ out)
{
    extern __shared__ char sm[];
    const int tid = threadIdx.x, lane = tid & 31, wid = tid >> 5;
    const int b = blockIdx.z, h = blockIdx.y;
    const int q0 = blockIdx.x * 128;
    const int bh = b * H_ + h;
    const __half* Qi_h = g_Qi + (size_t)bh * S_ * KH;
    const __half* Ki_h = g_Ki + (size_t)bh * S_ * KH;
    const __half* Vt_h = g_Vt + (size_t)bh * DH_ * (2 * S_);
    const uint32_t smu = smem_u32(sm);

    #pragma unroll
    for (int r = 0; r < 8; ++r) {
        int idx = tid + r * 256;                // 0..2047
        int row = idx >> 4, col = idx & 15;     // 128 rows x 16 16B-cols
        cpasync16(smu + QS_OFF + row * ASTR + col * 16,
                  Qi_h + (size_t)(q0 + row) * KH + col * 8);
    }
    attn_issue(smu, tid, 0, Ki_h, Vt_h);
    CP_COMMIT();
    attn_issue(smu, tid, 1, Ki_h, Vt_h);
    CP_COMMIT();

    const uint32_t faoff = (uint32_t)((wid * 16 + (lane & 15)) * ASTR +
                                      ((lane >> 4) & 1) * 16);
    const uint32_t fboff = (uint32_t)(((lane & 7) + ((lane & 16) >> 1)) * ASTR +
                                      (lane & 8) * 2);

    float ctx[8][4];
    #pragma unroll
    for (int i = 0; i < 8; ++i)
        #pragma unroll
        for (int j = 0; j < 4; ++j) ctx[i][j] = 0.f;
    float m0 = -1e30f, m1 = -1e30f, l0 = 0.f, l1 = 0.f;

    const int r0 = lane >> 2;
    const int srow0 = q0 + wid * 16 + r0;       // rows srow0 and srow0+8
    float* orow0 = out + ((size_t)(b * S_ + srow0) * H_ + h) * S_;
    float* orow1 = out + ((size_t)(b * S_ + srow0 + 8) * H_ + h) * S_;

    for (int kt = 0; kt < 16; ++kt) {
        CP_WAIT1();
        __syncthreads();

        const uint32_t kb = smu + KS_OFF + (uint32_t)(kt & 1) * KTILE;
        const uint32_t vb = smu + VS_OFF + (uint32_t)(kt & 1) * KTILE;

        // ---- QK^T over k'=128 ----
        float p[8][4];
        #pragma unroll
        for (int i = 0; i < 8; ++i)
            #pragma unroll
            for (int j = 0; j < 4; ++j) p[i][j] = 0.f;
        #pragma unroll
        for (int k16 = 0; k16 < 8; ++k16) {
            uint32_t a[4];
            ldsm4(a, smu + QS_OFF + faoff + k16 * 32);
            #pragma unroll
            for (int np = 0; np < 4; ++np) {
                uint32_t bv[4];
                ldsm4(bv, kb + fboff + np * 16 * ASTR + k16 * 32);
                mma_f16(p[np * 2 + 0], a, bv[0], bv[1]);
                mma_f16(p[np * 2 + 1], a, bv[2], bv[3]);
            }
        }

        // ---- scale + write raw scores (normalized later by the sweep) ----
        #pragma unroll
        for (int ni = 0; ni < 8; ++ni) {
            #pragma unroll
            for (int j = 0; j < 4; ++j) p[ni][j] *= SQK;
            const int c = kt * 64 + ni * 8 + (lane & 3) * 2;
            *(float2*)(orow0 + c) = make_float2(p[ni][0], p[ni][1]);
            *(float2*)(orow1 + c) = make_float2(p[ni][2], p[ni][3]);
        }

        // ---- online softmax; P pairs into Ps (warp-private rows) ----
        float mx0 = -1e30f, mx1 = -1e30f;
        #pragma unroll
        for (int ni = 0; ni < 8; ++ni) {
            mx0 = fmaxf(mx0, fmaxf(p[ni][0], p[ni][1]));
            mx1 = fmaxf(mx1, fmaxf(p[ni][2], p[ni][3]));
        }
        mx0 = fmaxf(mx0, __shfl_xor_sync(0xffffffffu, mx0, 1));
        mx0 = fmaxf(mx0, __shfl_xor_sync(0xffffffffu, mx0, 2));
        mx1 = fmaxf(mx1, __shfl_xor_sync(0xffffffffu, mx1, 1));
        mx1 = fmaxf(mx1, __shfl_xor_sync(0xffffffffu, mx1, 2));
        const float mn0 = fmaxf(m0, mx0), mn1 = fmaxf(m1, mx1);
        const float f0 = __expf(m0 - mn0), f1 = __expf(m1 - mn1);
        m0 = mn0; m1 = mn1;

        float s0 = 0.f, s1 = 0.f;
        const uint32_t psrow0 = smu + PS_OFF + (wid * 16 + r0) * ASTR;
        const uint32_t psrow1 = psrow0 + 8 * ASTR;
        #pragma unroll
        for (int ni = 0; ni < 8; ++ni) {
            const float e0 = __expf(p[ni][0] - mn0);
            const float e1 = __expf(p[ni][1] - mn0);
            const float e2 = __expf(p[ni][2] - mn1);
            const float e3 = __expf(p[ni][3] - mn1);
            s0 += e0 + e1; s1 += e2 + e3;
            const int cb = (ni * 8 + (lane & 3) * 2) * 4;   // byte offset 4*c
            uint32_t u[2];
            pack2(e0, e1, u);
            *(uint32_t*)(sm + (psrow0 - smu) + cb + 0) = u[0];
            *(uint32_t*)(sm + (psrow0 - smu) + cb + 4) = u[1];
            pack2(e2, e3, u);
            *(uint32_t*)(sm + (psrow1 - smu) + cb + 0) = u[0];
            *(uint32_t*)(sm + (psrow1 - smu) + cb + 4) = u[1];
        }
        s0 += __shfl_xor_sync(0xffffffffu, s0, 1);
        s0 += __shfl_xor_sync(0xffffffffu, s0, 2);
        s1 += __shfl_xor_sync(0xffffffffu, s1, 1);
        s1 += __shfl_xor_sync(0xffffffffu, s1, 2);
        l0 = l0 * f0 + s0;
        l1 = l1 * f1 + s1;
        #pragma unroll
        for (int ni = 0; ni < 8; ++ni) {
            ctx[ni][0] *= f0; ctx[ni][1] *= f0;
            ctx[ni][2] *= f1; ctx[ni][3] *= f1;
        }
        __syncwarp();   // Ps rows are warp-private; warp-level fence suffices

        // ---- PV over n'=128 ----
        #pragma unroll
        for (int k16 = 0; k16 < 8; ++k16) {
            uint32_t a[4];
            ldsm4(a, smu + PS_OFF + faoff + k16 * 32);
            #pragma unroll
            for (int np = 0; np < 4; ++np) {
                uint32_t bv[4];
                ldsm4(bv, vb + fboff + np * 16 * ASTR + k16 * 32);
                mma_f16(ctx[np * 2 + 0], a, bv[0], bv[1]);
                mma_f16(ctx[np * 2 + 1], a, bv[2], bv[3]);
            }
        }
        __syncthreads();   // all warps done with Ks/Vs this stage

        attn_issue(smu, tid, kt + 2, Ki_h, Vt_h);
        CP_COMMIT();
    }

    // ---- epilogue: ctx/l -> pairs into g_ai; (m, 1/l) into smem ----
    const float inv0 = 1.f / l0, inv1 = 1.f / l1;
    const int t0row = b * S_ + srow0;
    #pragma unroll
    for (int ni = 0; ni < 8; ++ni) {
        const int d = ni * 8 + (lane & 3) * 2;
        uint32_t u[2];
        pack2(ctx[ni][0] * inv0, ctx[ni][1] * inv0, u);
        uint2* dp = (uint2*)(g_ai + (size_t)t0row * KP + (h * 64 + d) * 2);
        *dp = make_uint2(u[0], u[1]);
        pack2(ctx[ni][2] * inv1, ctx[ni][3] * inv1, u);
        dp = (uint2*)(g_ai + (size_t)(t0row + 8) * KP + (h * 64 + d) * 2);
        *dp = make_uint2(u[0], u[1]);
    }

    // stash per-row (m, invl) in the dead Ps region: 128 rows x 2 floats
    float* mls = (float*)(sm + PS_OFF);
    if ((lane & 3) == 0) {
        const int lr = wid * 16 + r0;
        mls[2 * lr + 0] = m0;
        mls[2 * lr + 1] = inv0;
        mls[2 * (lr + 8) + 0] = m1;
        mls[2 * (lr + 8) + 1] = inv1;
    }
    __syncthreads();

    // ---- fused normw sweep: normalize this block's 128 score rows ----
    // Each warp owns rows [wid*16, wid*16+16); per row 1024 floats,
    // 32 lanes x float4 x 8 iters (coalesced 512B per access).
    for (int rr = 0; rr < 16; ++rr) {
        const int lr = wid * 16 + rr;
        const float m    = mls[2 * lr + 0];
        const float invl = mls[2 * lr + 1];
        float* row = out + ((size_t)(b * S_ + q0 + lr) * H_ + h) * S_;
        #pragma unroll
        for (int it = 0; it < 8; ++it) {
            const int c = it * 128 + lane * 4;
            float4 p4 = *(float4*)(row + c);
            p4.x = __expf(p4.x - m) * invl;
            p4.y = __expf(p4.y - m) * invl;
            p4.z = __expf(p4.z - m) * invl;
            p4.w = __expf(p4.w - m) * invl;
            *(float4*)(row + c) = p4;
        }
    }
}

// ====================================================================
// K5: LayerNorm. grid T, block 256.
// ====================================================================
__global__ void __launch_bounds__(256)
ln_kernel(const float* __restrict__ gamma, const float* __restrict__ beta,
          float* __restrict__ out)
{
    __shared__ float row[DM_];
    __shared__ float red[8];

    const int t = blockIdx.x;
    const int tid = threadIdx.x;

    float s = 0.f;
    #pragma unroll
    for (int j = 0; j < 3; j++) {
        float v = g_y[(size_t)t * DM_ + tid + j * 256];
        row[tid + j * 256] = v;
        s += v;
    }
    #pragma unroll
    for (int o = 16; o > 0; o >>= 1) s += __shfl_xor_sync(0xffffffffu, s, o);
    if ((tid & 31) == 0) red[tid >> 5] = s;
    __syncthreads();
    float tot = red[0];
    #pragma unroll
    for (int i = 1; i < 8; i++) tot += red[i];
    const float mu = tot * (1.0f / DM_);
    __syncthreads();

    float vs = 0.f;
    #pragma unroll
    for (int j = 0; j < 3; j++) {
        float d = row[tid + j * 256] - mu;
        vs += d * d;
    }
    #pragma unroll
    for (int o = 16; o > 0; o >>= 1) vs += __shfl_xor_sync(0xffffffffu, vs, o);
    if ((tid & 31) == 0) red[tid >> 5] = vs;
    __syncthreads();
    float tv = red[0];
    #pragma unroll
    for (int i = 1; i < 8; i++) tv += red[i];
    const float scale = rsqrtf(tv * (1.0f / DM_) + 1e-12f);

    #pragma unroll
    for (int j = 0; j < 3; j++) {
        const int idx = tid + j * 256;
        out[WOFF + (size_t)t * DM_ + idx] =
            (row[idx] - mu) * scale * gamma[idx] + beta[idx];
    }
}

// ====================================================================
// launch
// ====================================================================
extern "C" void kernel_launch(void* const* d_in, const int* in_sizes, int n_in,
                              void* d_out, int out_size)
{
    (void)in_sizes; (void)n_in; (void)out_size;
    const float* x     = (const float*)d_in[0];
    const float* Wq    = (const float*)d_in[1];
    const float* bq    = (const float*)d_in[2];
    const float* Wk    = (const float*)d_in[3];
    const float* bk    = (const float*)d_in[4];
    const float* Wv    = (const float*)d_in[5];
    const float* bv    = (const float*)d_in[6];
    const float* Wd    = (const float*)d_in[7];
    const float* bd    = (const float*)d_in[8];
    const float* gamma = (const float*)d_in[9];
    const float* beta  = (const float*)d_in[10];
    float* out = (float*)d_out;

    cudaFuncSetAttribute(qkv_mma,
                         cudaFuncAttributeMaxDynamicSharedMemorySize, SMEM_G);
    cudaFuncSetAttribute(dense_mma,
                         cudaFuncAttributeMaxDynamicSharedMemorySize, SMEM_G);
    cudaFuncSetAttribute(attn_mma,
                         cudaFuncAttributeMaxDynamicSharedMemorySize, SMEM_ATT);

    conv_x<<<T_ * E_ / 8 / 256, 256>>>(x);
    conv_w<<<dim3(E_ / 64, H_, 3), 256>>>(Wq, Wk, Wv);

    // z = 0,1,2: Q/K/V GEMMs; z = 3: folded conv_wd blocks
    qkv_mma<<<dim3(T_ / 128, DM_ / 128, 4), 256, SMEM_G>>>(bq, bk, bv, Wd);

    vtrans<<<dim3(S_ / 64, B_ * H_), 256>>>();

    attn_mma<<<dim3(S_ / 128, H_, B_), 256, SMEM_ATT>>>(out);

    dense_mma<<<dim3(T_ / 128, DM_ / 128), 256, SMEM_G>>>(bd);

    ln_kernel<<<T_, 256>>>(gamma, beta, out);
}